// round 1
// baseline (speedup 1.0000x reference)
#include <cuda_runtime.h>
#include <cuda_bf16.h>
#include <math.h>

// Problem dims (fixed)
#define BSZ 2
#define SEQ 2048
#define DMODEL 2048
#define NH 32
#define NKV 8
#define HDIM 64
// Derived
#define QDIM (NH * HDIM)    // 2048
#define KVDIM (NKV * HDIM)  // 512
#define TOKENS (BSZ * SEQ)  // 4096

// Scratch (static device globals; allocation is forbidden)
__device__ float g_q[(size_t)TOKENS * QDIM];     // 33.5 MB
__device__ float g_k[(size_t)TOKENS * KVDIM];    // 8.4 MB
__device__ float g_v[(size_t)TOKENS * KVDIM];    // 8.4 MB
__device__ float g_attn[(size_t)TOKENS * QDIM];  // 33.5 MB

// ---------------------------------------------------------------------------
// SGEMM: C[M,N] = A[M,K] @ B[K,N], all row-major fp32.
// 128x128 tile, BK=8, 256 threads, 8x8 per thread.
// M,N multiples of 128; K multiple of 8 (true for all our shapes).
// ---------------------------------------------------------------------------
__global__ __launch_bounds__(256) void sgemm128(const float* __restrict__ A,
                                                const float* __restrict__ B,
                                                float* __restrict__ C,
                                                int M, int N, int K) {
    __shared__ float As[8][128];  // transposed: As[k][m]
    __shared__ float Bs[8][128];  // Bs[k][n]

    const int tid = threadIdx.x;
    const int bx = blockIdx.x;  // over N
    const int by = blockIdx.y;  // over M
    const int tx = tid & 15;
    const int ty = tid >> 4;

    const float* Ab = A + (size_t)by * 128 * K;
    const float* Bb = B + (size_t)bx * 128;

    const int arow = tid >> 1;         // 0..127
    const int ak4 = (tid & 1) * 4;     // 0 or 4
    const int brow = tid >> 5;         // 0..7
    const int bcol = (tid & 31) * 4;   // 0..124

    float acc[8][8];
#pragma unroll
    for (int i = 0; i < 8; i++)
#pragma unroll
        for (int j = 0; j < 8; j++) acc[i][j] = 0.0f;

    for (int k0 = 0; k0 < K; k0 += 8) {
        float4 a4 = *(const float4*)(Ab + (size_t)arow * K + k0 + ak4);
        float4 b4 = *(const float4*)(Bb + (size_t)(k0 + brow) * N + bcol);
        __syncthreads();  // previous compute done before overwriting smem
        As[ak4 + 0][arow] = a4.x;
        As[ak4 + 1][arow] = a4.y;
        As[ak4 + 2][arow] = a4.z;
        As[ak4 + 3][arow] = a4.w;
        *(float4*)&Bs[brow][bcol] = b4;
        __syncthreads();
#pragma unroll
        for (int kk = 0; kk < 8; kk++) {
            float af[8], bf[8];
            *(float4*)(af) = *(const float4*)&As[kk][ty * 8];
            *(float4*)(af + 4) = *(const float4*)&As[kk][ty * 8 + 4];
            *(float4*)(bf) = *(const float4*)&Bs[kk][tx * 8];
            *(float4*)(bf + 4) = *(const float4*)&Bs[kk][tx * 8 + 4];
#pragma unroll
            for (int i = 0; i < 8; i++)
#pragma unroll
                for (int j = 0; j < 8; j++) acc[i][j] = fmaf(af[i], bf[j], acc[i][j]);
        }
    }

    float* Cb = C + (size_t)(by * 128 + ty * 8) * N + bx * 128 + tx * 8;
#pragma unroll
    for (int i = 0; i < 8; i++) {
        float4 o0 = make_float4(acc[i][0], acc[i][1], acc[i][2], acc[i][3]);
        float4 o1 = make_float4(acc[i][4], acc[i][5], acc[i][6], acc[i][7]);
        *(float4*)(Cb + (size_t)i * N) = o0;
        *(float4*)(Cb + (size_t)i * N + 4) = o1;
    }
}

// ---------------------------------------------------------------------------
// RoPE (interleaved pairs, Llama-style), in place on [TOKENS, nh, 64].
// One thread per (token, head, pair).
// ---------------------------------------------------------------------------
__global__ void rope_kernel(float* __restrict__ x, const float* __restrict__ fc,
                            const float* __restrict__ fs, int nh, int total) {
    int idx = blockIdx.x * blockDim.x + threadIdx.x;
    if (idx >= total) return;
    int j = idx & 31;        // pair index 0..31
    int t = idx >> 5;        // token*nh + head
    int tok = t / nh;        // b*SEQ + s
    int s = tok & (SEQ - 1);
    float c = fc[s * 32 + j];
    float si = fs[s * 32 + j];
    float* p = x + (size_t)t * HDIM + 2 * j;
    float x1 = p[0];
    float x2 = p[1];
    p[0] = x1 * c - x2 * si;
    p[1] = x1 * si + x2 * c;
}

// ---------------------------------------------------------------------------
// Causal flash attention with GQA.
// Block = one (q-tile of 64, head, batch). 256 threads: 16x16, 4x4 per thread.
// Q layout [TOKENS, NH*64]; K,V [TOKENS, NKV*64]; out [TOKENS, NH*64].
// Dynamic smem: Qs | Ks(aliased as P) | Vs, each 64*65 floats.
// ---------------------------------------------------------------------------
#define AS 65
__global__ __launch_bounds__(256) void flash_kernel(const float* __restrict__ Q,
                                                    const float* __restrict__ Kg,
                                                    const float* __restrict__ Vg,
                                                    float* __restrict__ O) {
    extern __shared__ float sm[];
    float* Qs = sm;
    float* Ks = sm + 64 * AS;  // also reused as P after scores are consumed
    float* Vs = sm + 2 * 64 * AS;

    const int qt = blockIdx.x;
    const int h = blockIdx.y;
    const int b = blockIdx.z;
    const int g = h >> 2;  // kv head = h / (NH/NKV)
    const int tid = threadIdx.x;
    const int tx = tid & 15;
    const int ty = tid >> 4;
    const int q0 = qt * 64;
    const int r0 = ty * 4;
    const int c0 = tx * 4;

    // Load Q tile (64 x 64)
    const float* qbase = Q + ((size_t)b * SEQ + q0) * QDIM + h * HDIM;
    for (int i = tid; i < 64 * 16; i += 256) {
        int r = i >> 4;
        int c = (i & 15) * 4;
        float4 t = *(const float4*)(qbase + (size_t)r * QDIM + c);
        Qs[r * AS + c] = t.x;
        Qs[r * AS + c + 1] = t.y;
        Qs[r * AS + c + 2] = t.z;
        Qs[r * AS + c + 3] = t.w;
    }

    float m[4], l[4], acc[4][4];
#pragma unroll
    for (int i = 0; i < 4; i++) {
        m[i] = -1e30f;
        l[i] = 0.0f;
#pragma unroll
        for (int j = 0; j < 4; j++) acc[i][j] = 0.0f;
    }

    for (int kt = 0; kt <= qt; ++kt) {
        __syncthreads();  // previous PV reads done before refilling Ks/Vs
        const float* kbase = Kg + ((size_t)b * SEQ + kt * 64) * KVDIM + g * HDIM;
        const float* vbase = Vg + ((size_t)b * SEQ + kt * 64) * KVDIM + g * HDIM;
        for (int i = tid; i < 64 * 16; i += 256) {
            int r = i >> 4;
            int c = (i & 15) * 4;
            float4 t = *(const float4*)(kbase + (size_t)r * KVDIM + c);
            Ks[r * AS + c] = t.x;
            Ks[r * AS + c + 1] = t.y;
            Ks[r * AS + c + 2] = t.z;
            Ks[r * AS + c + 3] = t.w;
            float4 u = *(const float4*)(vbase + (size_t)r * KVDIM + c);
            Vs[r * AS + c] = u.x;
            Vs[r * AS + c + 1] = u.y;
            Vs[r * AS + c + 2] = u.z;
            Vs[r * AS + c + 3] = u.w;
        }
        __syncthreads();

        // S = Q K^T (4x4 per thread)
        float s[4][4];
#pragma unroll
        for (int i = 0; i < 4; i++)
#pragma unroll
            for (int j = 0; j < 4; j++) s[i][j] = 0.0f;
#pragma unroll 8
        for (int d = 0; d < 64; ++d) {
            float qv[4], kv[4];
#pragma unroll
            for (int i = 0; i < 4; i++) qv[i] = Qs[(r0 + i) * AS + d];
#pragma unroll
            for (int j = 0; j < 4; j++) kv[j] = Ks[(c0 + j) * AS + d];
#pragma unroll
            for (int i = 0; i < 4; i++)
#pragma unroll
                for (int j = 0; j < 4; j++) s[i][j] = fmaf(qv[i], kv[j], s[i][j]);
        }

        // scale + causal mask (diagonal tile only)
        if (kt == qt) {
#pragma unroll
            for (int i = 0; i < 4; i++)
#pragma unroll
                for (int j = 0; j < 4; j++)
                    s[i][j] = (c0 + j > r0 + i) ? -1e30f : s[i][j] * 0.125f;
        } else {
#pragma unroll
            for (int i = 0; i < 4; i++)
#pragma unroll
                for (int j = 0; j < 4; j++) s[i][j] *= 0.125f;
        }

        // online softmax update
        float p[4][4];
#pragma unroll
        for (int i = 0; i < 4; i++) {
            float mt = fmaxf(fmaxf(s[i][0], s[i][1]), fmaxf(s[i][2], s[i][3]));
            mt = fmaxf(mt, __shfl_xor_sync(0xffffffffu, mt, 1));
            mt = fmaxf(mt, __shfl_xor_sync(0xffffffffu, mt, 2));
            mt = fmaxf(mt, __shfl_xor_sync(0xffffffffu, mt, 4));
            mt = fmaxf(mt, __shfl_xor_sync(0xffffffffu, mt, 8));
            float mn = fmaxf(m[i], mt);
            float resc = __expf(m[i] - mn);
            float rs = 0.0f;
#pragma unroll
            for (int j = 0; j < 4; j++) {
                p[i][j] = __expf(s[i][j] - mn);
                rs += p[i][j];
            }
            rs += __shfl_xor_sync(0xffffffffu, rs, 1);
            rs += __shfl_xor_sync(0xffffffffu, rs, 2);
            rs += __shfl_xor_sync(0xffffffffu, rs, 4);
            rs += __shfl_xor_sync(0xffffffffu, rs, 8);
            l[i] = l[i] * resc + rs;
            m[i] = mn;
#pragma unroll
            for (int j = 0; j < 4; j++) acc[i][j] *= resc;
        }

        __syncthreads();  // all threads done reading Ks before it becomes P
#pragma unroll
        for (int i = 0; i < 4; i++)
#pragma unroll
            for (int j = 0; j < 4; j++) Ks[(r0 + i) * AS + c0 + j] = p[i][j];
        __syncthreads();

        // O += P @ V  (P lives in Ks)
#pragma unroll 8
        for (int c = 0; c < 64; ++c) {
            float pv[4], vv[4];
#pragma unroll
            for (int i = 0; i < 4; i++) pv[i] = Ks[(r0 + i) * AS + c];
#pragma unroll
            for (int j = 0; j < 4; j++) vv[j] = Vs[c * AS + c0 + j];
#pragma unroll
            for (int i = 0; i < 4; i++)
#pragma unroll
                for (int j = 0; j < 4; j++) acc[i][j] = fmaf(pv[i], vv[j], acc[i][j]);
        }
    }

    // normalize + write
#pragma unroll
    for (int i = 0; i < 4; i++) {
        float inv = 1.0f / l[i];
        float4 o = make_float4(acc[i][0] * inv, acc[i][1] * inv, acc[i][2] * inv,
                               acc[i][3] * inv);
        *(float4*)(O + ((size_t)b * SEQ + q0 + r0 + i) * QDIM + h * HDIM + c0) = o;
    }
}

// ---------------------------------------------------------------------------
// Launch
// ---------------------------------------------------------------------------
extern "C" void kernel_launch(void* const* d_in, const int* in_sizes, int n_in,
                              void* d_out, int out_size) {
    const float* x = (const float*)d_in[0];
    const float* wq = (const float*)d_in[1];
    const float* wk = (const float*)d_in[2];
    const float* wv = (const float*)d_in[3];
    const float* wo = (const float*)d_in[4];
    const float* fc = (const float*)d_in[5];
    const float* fs = (const float*)d_in[6];
    float* out = (float*)d_out;

    float *q, *k, *v, *attn;
    cudaGetSymbolAddress((void**)&q, g_q);
    cudaGetSymbolAddress((void**)&k, g_k);
    cudaGetSymbolAddress((void**)&v, g_v);
    cudaGetSymbolAddress((void**)&attn, g_attn);

    // QKV projections
    sgemm128<<<dim3(QDIM / 128, TOKENS / 128), 256>>>(x, wq, q, TOKENS, QDIM, DMODEL);
    sgemm128<<<dim3(KVDIM / 128, TOKENS / 128), 256>>>(x, wk, k, TOKENS, KVDIM, DMODEL);
    sgemm128<<<dim3(KVDIM / 128, TOKENS / 128), 256>>>(x, wv, v, TOKENS, KVDIM, DMODEL);

    // RoPE on q and k
    {
        int totq = TOKENS * NH * (HDIM / 2);
        rope_kernel<<<(totq + 255) / 256, 256>>>(q, fc, fs, NH, totq);
        int totk = TOKENS * NKV * (HDIM / 2);
        rope_kernel<<<(totk + 255) / 256, 256>>>(k, fc, fs, NKV, totk);
    }

    // Flash attention
    {
        int smem = 3 * 64 * AS * sizeof(float);  // 49920 B
        cudaFuncSetAttribute(flash_kernel, cudaFuncAttributeMaxDynamicSharedMemorySize,
                             smem);
        flash_kernel<<<dim3(SEQ / 64, NH, BSZ), 256, smem>>>(q, k, v, attn);
    }

    // Output projection
    sgemm128<<<dim3(DMODEL / 128, TOKENS / 128), 256>>>(attn, wo, out, TOKENS, DMODEL,
                                                        DMODEL);
}

// round 4
// speedup vs baseline: 2.1948x; 2.1948x over previous
#include <cuda_runtime.h>
#include <cuda_fp16.h>
#include <cuda_bf16.h>
#include <math.h>
#include <stdint.h>

// Problem dims (fixed)
#define BSZ 2
#define SEQ 2048
#define DMODEL 2048
#define NH 32
#define NKV 8
#define HDIM 64
#define QDIM (NH * HDIM)    // 2048
#define KVDIM (NKV * HDIM)  // 512
#define TOKENS (BSZ * SEQ)  // 4096

// Scratch (static device globals; allocation is forbidden)
__device__ float g_q[(size_t)TOKENS * QDIM];
__device__ float g_k[(size_t)TOKENS * KVDIM];
__device__ float g_v[(size_t)TOKENS * KVDIM];
__device__ float g_attn[(size_t)TOKENS * QDIM];
__device__ __half g_xh[(size_t)TOKENS * DMODEL];
__device__ __half g_attnh[(size_t)TOKENS * QDIM];
__device__ __half g_wqTh[(size_t)QDIM * DMODEL];   // [N][K]
__device__ __half g_wkTh[(size_t)KVDIM * DMODEL];
__device__ __half g_wvTh[(size_t)KVDIM * DMODEL];
__device__ __half g_woTh[(size_t)DMODEL * QDIM];

// ---------------------------------------------------------------------------
// fp16 GEMM via mma.sync (sm_80-class path; available on plain sm_100 target).
// C[M,N] = A[M,K] @ B[N,K]^T.  A,B fp16 row-major (K contiguous), C fp32.
// CTA 128x128, BK=32, 256 threads = 8 warps (4m x 2n), warp tile 32x64.
// Smem XOR-swizzled so all fragment LDS.32 loads are bank-conflict-free.
// ---------------------------------------------------------------------------
__global__ __launch_bounds__(256) void hgemm(const __half* __restrict__ A,
                                             const __half* __restrict__ B,
                                             float* __restrict__ C, int M, int N,
                                             int K) {
    __shared__ __half As[2][128][32];
    __shared__ __half Bs[2][128][32];

    const int tid = threadIdx.x;
    const int wid = tid >> 5;
    const int lane = tid & 31;
    const int wm = wid & 3;   // 0..3 (m)
    const int wn = wid >> 2;  // 0..1 (n)
    const int r = lane >> 2;  // 0..7
    const int tig = lane & 3; // 0..3
    const int bx = blockIdx.x;
    const int by = blockIdx.y;

    const __half* Ab = A + (size_t)by * 128 * K;
    const __half* Bb = B + (size_t)bx * 128 * K;

    float acc[2][8][4];
#pragma unroll
    for (int mt = 0; mt < 2; mt++)
#pragma unroll
        for (int nt = 0; nt < 8; nt++)
#pragma unroll
            for (int i = 0; i < 4; i++) acc[mt][nt][i] = 0.0f;

// 512 16B-chunks per tile (128 rows x 4 chunks); each thread copies 2 per matrix.
#define LOAD_TILE(buf, k0)                                                            \
    {                                                                                 \
        for (int i = 0; i < 2; i++) {                                                 \
            int cl = tid + i * 256;                                                   \
            int row = cl >> 2;                                                        \
            int c = cl & 3;                                                           \
            int phys = (c ^ ((row >> 1) & 3)) * 8;                                    \
            uint32_t da = (uint32_t)__cvta_generic_to_shared(&As[buf][row][phys]);    \
            const __half* sa = Ab + (size_t)row * K + (k0) + c * 8;                   \
            asm volatile("cp.async.cg.shared.global [%0], [%1], 16;" ::"r"(da),       \
                         "l"(sa));                                                    \
            uint32_t db = (uint32_t)__cvta_generic_to_shared(&Bs[buf][row][phys]);    \
            const __half* sb = Bb + (size_t)row * K + (k0) + c * 8;                   \
            asm volatile("cp.async.cg.shared.global [%0], [%1], 16;" ::"r"(db),       \
                         "l"(sb));                                                    \
        }                                                                             \
    }

    LOAD_TILE(0, 0);
    asm volatile("cp.async.commit_group;");

    const int nk = K >> 5;
    for (int kt = 0; kt < nk; kt++) {
        const int buf = kt & 1;
        if (kt + 1 < nk) LOAD_TILE(buf ^ 1, (kt + 1) * 32);
        asm volatile("cp.async.commit_group;");
        asm volatile("cp.async.wait_group 1;");
        __syncthreads();

#pragma unroll
        for (int ks = 0; ks < 2; ks++) {
            const int c0 = ks * 2, c1 = ks * 2 + 1;
            uint32_t a[2][4], b[8][2];
#pragma unroll
            for (int mt = 0; mt < 2; mt++) {
                int r0 = wm * 32 + mt * 16 + r;
                int r1 = r0 + 8;
                int s0 = (r0 >> 1) & 3, s1 = (r1 >> 1) & 3;
                a[mt][0] = *(const uint32_t*)&As[buf][r0][(c0 ^ s0) * 8 + tig * 2];
                a[mt][1] = *(const uint32_t*)&As[buf][r1][(c0 ^ s1) * 8 + tig * 2];
                a[mt][2] = *(const uint32_t*)&As[buf][r0][(c1 ^ s0) * 8 + tig * 2];
                a[mt][3] = *(const uint32_t*)&As[buf][r1][(c1 ^ s1) * 8 + tig * 2];
            }
#pragma unroll
            for (int nt = 0; nt < 8; nt++) {
                int n0 = wn * 64 + nt * 8 + r;
                int sn = (n0 >> 1) & 3;
                b[nt][0] = *(const uint32_t*)&Bs[buf][n0][(c0 ^ sn) * 8 + tig * 2];
                b[nt][1] = *(const uint32_t*)&Bs[buf][n0][(c1 ^ sn) * 8 + tig * 2];
            }
#pragma unroll
            for (int mt = 0; mt < 2; mt++)
#pragma unroll
                for (int nt = 0; nt < 8; nt++)
                    asm volatile(
                        "mma.sync.aligned.m16n8k16.row.col.f32.f16.f16.f32 "
                        "{%0,%1,%2,%3}, {%4,%5,%6,%7}, {%8,%9}, {%0,%1,%2,%3};"
                        : "+f"(acc[mt][nt][0]), "+f"(acc[mt][nt][1]),
                          "+f"(acc[mt][nt][2]), "+f"(acc[mt][nt][3])
                        : "r"(a[mt][0]), "r"(a[mt][1]), "r"(a[mt][2]), "r"(a[mt][3]),
                          "r"(b[nt][0]), "r"(b[nt][1]));
        }
        __syncthreads();
    }

#pragma unroll
    for (int mt = 0; mt < 2; mt++) {
        int row = by * 128 + wm * 32 + mt * 16 + r;
#pragma unroll
        for (int nt = 0; nt < 8; nt++) {
            int col = bx * 128 + wn * 64 + nt * 8 + tig * 2;
            *(float2*)&C[(size_t)row * N + col] =
                make_float2(acc[mt][nt][0], acc[mt][nt][1]);
            *(float2*)&C[(size_t)(row + 8) * N + col] =
                make_float2(acc[mt][nt][2], acc[mt][nt][3]);
        }
    }
#undef LOAD_TILE
}

// ---------------------------------------------------------------------------
// fp32 -> fp16 elementwise convert (n divisible by 4)
// ---------------------------------------------------------------------------
__global__ void f32_to_f16(const float* __restrict__ in, __half* __restrict__ out,
                           int n) {
    int i = (blockIdx.x * blockDim.x + threadIdx.x) * 4;
    if (i >= n) return;
    float4 v = *(const float4*)(in + i);
    *(__half2*)(out + i) = __floats2half2_rn(v.x, v.y);
    *(__half2*)(out + i + 2) = __floats2half2_rn(v.z, v.w);
}

// ---------------------------------------------------------------------------
// Transpose + convert: out[C][R] (fp16) = in[R][C] (fp32)
// ---------------------------------------------------------------------------
__global__ void transpose_f16(const float* __restrict__ in, __half* __restrict__ out,
                              int R, int C) {
    __shared__ float t[32][33];
    int bx = blockIdx.x * 32, by = blockIdx.y * 32;
    int x = bx + threadIdx.x;
    for (int i = threadIdx.y; i < 32; i += 8)
        t[i][threadIdx.x] = in[(size_t)(by + i) * C + x];
    __syncthreads();
    int ox = by + threadIdx.x;
    for (int i = threadIdx.y; i < 32; i += 8)
        out[(size_t)(bx + i) * R + ox] = __float2half_rn(t[threadIdx.x][i]);
}

// ---------------------------------------------------------------------------
// RoPE (interleaved pairs), in place on [TOKENS, nh, 64] fp32.
// ---------------------------------------------------------------------------
__global__ void rope_kernel(float* __restrict__ x, const float* __restrict__ fc,
                            const float* __restrict__ fs, int nh, int total) {
    int idx = blockIdx.x * blockDim.x + threadIdx.x;
    if (idx >= total) return;
    int j = idx & 31;
    int t = idx >> 5;
    int tok = t / nh;
    int s = tok & (SEQ - 1);
    float c = fc[s * 32 + j];
    float si = fs[s * 32 + j];
    float* p = x + (size_t)t * HDIM + 2 * j;
    float x1 = p[0];
    float x2 = p[1];
    p[0] = x1 * c - x2 * si;
    p[1] = x1 * si + x2 * c;
}

// ---------------------------------------------------------------------------
// Causal flash attention with GQA (fp32, known-correct from round 1).
// ---------------------------------------------------------------------------
#define AS 65
__global__ __launch_bounds__(256) void flash_kernel(const float* __restrict__ Q,
                                                    const float* __restrict__ Kg,
                                                    const float* __restrict__ Vg,
                                                    float* __restrict__ O) {
    extern __shared__ float sm[];
    float* Qs = sm;
    float* Ks = sm + 64 * AS;
    float* Vs = sm + 2 * 64 * AS;

    const int qt = blockIdx.x;
    const int h = blockIdx.y;
    const int b = blockIdx.z;
    const int g = h >> 2;
    const int tid = threadIdx.x;
    const int tx = tid & 15;
    const int ty = tid >> 4;
    const int q0 = qt * 64;
    const int r0 = ty * 4;
    const int c0 = tx * 4;

    const float* qbase = Q + ((size_t)b * SEQ + q0) * QDIM + h * HDIM;
    for (int i = tid; i < 64 * 16; i += 256) {
        int r = i >> 4;
        int c = (i & 15) * 4;
        float4 t = *(const float4*)(qbase + (size_t)r * QDIM + c);
        Qs[r * AS + c] = t.x;
        Qs[r * AS + c + 1] = t.y;
        Qs[r * AS + c + 2] = t.z;
        Qs[r * AS + c + 3] = t.w;
    }

    float m[4], l[4], acc[4][4];
#pragma unroll
    for (int i = 0; i < 4; i++) {
        m[i] = -1e30f;
        l[i] = 0.0f;
#pragma unroll
        for (int j = 0; j < 4; j++) acc[i][j] = 0.0f;
    }

    for (int kt = 0; kt <= qt; ++kt) {
        __syncthreads();
        const float* kbase = Kg + ((size_t)b * SEQ + kt * 64) * KVDIM + g * HDIM;
        const float* vbase = Vg + ((size_t)b * SEQ + kt * 64) * KVDIM + g * HDIM;
        for (int i = tid; i < 64 * 16; i += 256) {
            int r = i >> 4;
            int c = (i & 15) * 4;
            float4 t = *(const float4*)(kbase + (size_t)r * KVDIM + c);
            Ks[r * AS + c] = t.x;
            Ks[r * AS + c + 1] = t.y;
            Ks[r * AS + c + 2] = t.z;
            Ks[r * AS + c + 3] = t.w;
            float4 u = *(const float4*)(vbase + (size_t)r * KVDIM + c);
            Vs[r * AS + c] = u.x;
            Vs[r * AS + c + 1] = u.y;
            Vs[r * AS + c + 2] = u.z;
            Vs[r * AS + c + 3] = u.w;
        }
        __syncthreads();

        float s[4][4];
#pragma unroll
        for (int i = 0; i < 4; i++)
#pragma unroll
            for (int j = 0; j < 4; j++) s[i][j] = 0.0f;
#pragma unroll 8
        for (int d = 0; d < 64; ++d) {
            float qv[4], kv[4];
#pragma unroll
            for (int i = 0; i < 4; i++) qv[i] = Qs[(r0 + i) * AS + d];
#pragma unroll
            for (int j = 0; j < 4; j++) kv[j] = Ks[(c0 + j) * AS + d];
#pragma unroll
            for (int i = 0; i < 4; i++)
#pragma unroll
                for (int j = 0; j < 4; j++) s[i][j] = fmaf(qv[i], kv[j], s[i][j]);
        }

        if (kt == qt) {
#pragma unroll
            for (int i = 0; i < 4; i++)
#pragma unroll
                for (int j = 0; j < 4; j++)
                    s[i][j] = (c0 + j > r0 + i) ? -1e30f : s[i][j] * 0.125f;
        } else {
#pragma unroll
            for (int i = 0; i < 4; i++)
#pragma unroll
                for (int j = 0; j < 4; j++) s[i][j] *= 0.125f;
        }

        float p[4][4];
#pragma unroll
        for (int i = 0; i < 4; i++) {
            float mt = fmaxf(fmaxf(s[i][0], s[i][1]), fmaxf(s[i][2], s[i][3]));
            mt = fmaxf(mt, __shfl_xor_sync(0xffffffffu, mt, 1));
            mt = fmaxf(mt, __shfl_xor_sync(0xffffffffu, mt, 2));
            mt = fmaxf(mt, __shfl_xor_sync(0xffffffffu, mt, 4));
            mt = fmaxf(mt, __shfl_xor_sync(0xffffffffu, mt, 8));
            float mn = fmaxf(m[i], mt);
            float resc = __expf(m[i] - mn);
            float rs = 0.0f;
#pragma unroll
            for (int j = 0; j < 4; j++) {
                p[i][j] = __expf(s[i][j] - mn);
                rs += p[i][j];
            }
            rs += __shfl_xor_sync(0xffffffffu, rs, 1);
            rs += __shfl_xor_sync(0xffffffffu, rs, 2);
            rs += __shfl_xor_sync(0xffffffffu, rs, 4);
            rs += __shfl_xor_sync(0xffffffffu, rs, 8);
            l[i] = l[i] * resc + rs;
            m[i] = mn;
#pragma unroll
            for (int j = 0; j < 4; j++) acc[i][j] *= resc;
        }

        __syncthreads();
#pragma unroll
        for (int i = 0; i < 4; i++)
#pragma unroll
            for (int j = 0; j < 4; j++) Ks[(r0 + i) * AS + c0 + j] = p[i][j];
        __syncthreads();

#pragma unroll 8
        for (int c = 0; c < 64; ++c) {
            float pv[4], vv[4];
#pragma unroll
            for (int i = 0; i < 4; i++) pv[i] = Ks[(r0 + i) * AS + c];
#pragma unroll
            for (int j = 0; j < 4; j++) vv[j] = Vs[c * AS + c0 + j];
#pragma unroll
            for (int i = 0; i < 4; i++)
#pragma unroll
                for (int j = 0; j < 4; j++) acc[i][j] = fmaf(pv[i], vv[j], acc[i][j]);
        }
    }

#pragma unroll
    for (int i = 0; i < 4; i++) {
        float inv = 1.0f / l[i];
        float4 o = make_float4(acc[i][0] * inv, acc[i][1] * inv, acc[i][2] * inv,
                               acc[i][3] * inv);
        *(float4*)(O + ((size_t)b * SEQ + q0 + r0 + i) * QDIM + h * HDIM + c0) = o;
    }
}

// ---------------------------------------------------------------------------
// Launch
// ---------------------------------------------------------------------------
extern "C" void kernel_launch(void* const* d_in, const int* in_sizes, int n_in,
                              void* d_out, int out_size) {
    const float* x = (const float*)d_in[0];
    const float* wq = (const float*)d_in[1];
    const float* wk = (const float*)d_in[2];
    const float* wv = (const float*)d_in[3];
    const float* wo = (const float*)d_in[4];
    const float* fc = (const float*)d_in[5];
    const float* fs = (const float*)d_in[6];
    float* out = (float*)d_out;

    float *q, *k, *v, *attn;
    __half *xh, *attnh, *wqTh, *wkTh, *wvTh, *woTh;
    cudaGetSymbolAddress((void**)&q, g_q);
    cudaGetSymbolAddress((void**)&k, g_k);
    cudaGetSymbolAddress((void**)&v, g_v);
    cudaGetSymbolAddress((void**)&attn, g_attn);
    cudaGetSymbolAddress((void**)&xh, g_xh);
    cudaGetSymbolAddress((void**)&attnh, g_attnh);
    cudaGetSymbolAddress((void**)&wqTh, g_wqTh);
    cudaGetSymbolAddress((void**)&wkTh, g_wkTh);
    cudaGetSymbolAddress((void**)&wvTh, g_wvTh);
    cudaGetSymbolAddress((void**)&woTh, g_woTh);

    // Convert x to fp16; transpose+convert weights to [N][K] fp16.
    {
        int n = TOKENS * DMODEL;
        f32_to_f16<<<(n / 4 + 255) / 256, 256>>>(x, xh, n);
    }
    transpose_f16<<<dim3(QDIM / 32, DMODEL / 32), dim3(32, 8)>>>(wq, wqTh, DMODEL,
                                                                 QDIM);
    transpose_f16<<<dim3(KVDIM / 32, DMODEL / 32), dim3(32, 8)>>>(wk, wkTh, DMODEL,
                                                                  KVDIM);
    transpose_f16<<<dim3(KVDIM / 32, DMODEL / 32), dim3(32, 8)>>>(wv, wvTh, DMODEL,
                                                                  KVDIM);
    transpose_f16<<<dim3(DMODEL / 32, QDIM / 32), dim3(32, 8)>>>(wo, woTh, QDIM,
                                                                 DMODEL);

    // QKV projections (fp16 tensor cores, fp32 accumulate)
    hgemm<<<dim3(QDIM / 128, TOKENS / 128), 256>>>(xh, wqTh, q, TOKENS, QDIM, DMODEL);
    hgemm<<<dim3(KVDIM / 128, TOKENS / 128), 256>>>(xh, wkTh, k, TOKENS, KVDIM,
                                                    DMODEL);
    hgemm<<<dim3(KVDIM / 128, TOKENS / 128), 256>>>(xh, wvTh, v, TOKENS, KVDIM,
                                                    DMODEL);

    // RoPE (fp32)
    {
        int totq = TOKENS * NH * (HDIM / 2);
        rope_kernel<<<(totq + 255) / 256, 256>>>(q, fc, fs, NH, totq);
        int totk = TOKENS * NKV * (HDIM / 2);
        rope_kernel<<<(totk + 255) / 256, 256>>>(k, fc, fs, NKV, totk);
    }

    // Flash attention (fp32)
    {
        int smem = 3 * 64 * AS * sizeof(float);
        cudaFuncSetAttribute(flash_kernel, cudaFuncAttributeMaxDynamicSharedMemorySize,
                             smem);
        flash_kernel<<<dim3(SEQ / 64, NH, BSZ), 256, smem>>>(q, k, v, attn);
    }

    // Output projection
    {
        int n = TOKENS * QDIM;
        f32_to_f16<<<(n / 4 + 255) / 256, 256>>>(attn, attnh, n);
    }
    hgemm<<<dim3(DMODEL / 128, TOKENS / 128), 256>>>(attnh, woTh, out, TOKENS, DMODEL,
                                                     QDIM);
}

// round 5
// speedup vs baseline: 6.0202x; 2.7430x over previous
#include <cuda_runtime.h>
#include <cuda_fp16.h>
#include <cuda_bf16.h>
#include <math.h>
#include <stdint.h>

// Problem dims (fixed)
#define BSZ 2
#define SEQ 2048
#define DMODEL 2048
#define NH 32
#define NKV 8
#define HDIM 64
#define QDIM (NH * HDIM)    // 2048
#define KVDIM (NKV * HDIM)  // 512
#define TOKENS (BSZ * SEQ)  // 4096

// scale = 1/sqrt(64) * log2(e)
#define SCL 0.1803368801111204f

// Scratch (static device globals; allocation is forbidden)
__device__ float g_q[(size_t)TOKENS * QDIM];
__device__ float g_k[(size_t)TOKENS * KVDIM];
__device__ float g_v[(size_t)TOKENS * KVDIM];
__device__ __half g_xh[(size_t)TOKENS * DMODEL];
__device__ __half g_attnh[(size_t)TOKENS * QDIM];
__device__ __half g_qh[(size_t)TOKENS * QDIM];    // [B][NH][S][64]
__device__ __half g_kh[(size_t)TOKENS * KVDIM];   // [B][NKV][S][64]
__device__ __half g_vth[(size_t)TOKENS * KVDIM];  // [B][NKV][64][S]
__device__ __half g_wqTh[(size_t)QDIM * DMODEL];  // [N][K]
__device__ __half g_wkTh[(size_t)KVDIM * DMODEL];
__device__ __half g_wvTh[(size_t)KVDIM * DMODEL];
__device__ __half g_woTh[(size_t)DMODEL * QDIM];

#define MMA16816(d, a0, a1, a2, a3, b0, b1)                            \
    asm volatile(                                                      \
        "mma.sync.aligned.m16n8k16.row.col.f32.f16.f16.f32 "           \
        "{%0,%1,%2,%3}, {%4,%5,%6,%7}, {%8,%9}, {%0,%1,%2,%3};"        \
        : "+f"((d)[0]), "+f"((d)[1]), "+f"((d)[2]), "+f"((d)[3])       \
        : "r"(a0), "r"(a1), "r"(a2), "r"(a3), "r"(b0), "r"(b1))

#define CPASYNC16(smem_half_ptr, gptr)                                          \
    asm volatile("cp.async.cg.shared.global [%0], [%1], 16;" ::"r"(             \
                     (uint32_t)__cvta_generic_to_shared(smem_half_ptr)),        \
                 "l"(gptr))

// exp2 on FMA/ALU pipes (x <= 0 expected; clamped to >= -126)
__device__ __forceinline__ float fast_exp2(float x) {
    x = fmaxf(x, -126.0f);
    float z = x + 12582912.0f;  // 1.5 * 2^23
    int n = __float_as_int(z) << 23;
    float f = x - (z - 12582912.0f);  // f in [-0.5, 0.5]
    float y = 0.0013276471f;
    y = fmaf(y, f, 0.0096181993f);
    y = fmaf(y, f, 0.0555041086f);
    y = fmaf(y, f, 0.2402264923f);
    y = fmaf(y, f, 0.6931471825f);
    y = fmaf(y, f, 1.0f);
    return __int_as_float(__float_as_int(y) + n);
}

// swizzled index of half element (r, c) in a [64][64] tile
__device__ __forceinline__ int swi(int r, int c) {
    return r * 64 + ((((c >> 3) ^ (r & 7)) << 3) + (c & 7));
}

// ---------------------------------------------------------------------------
// fp16 GEMM via mma.sync.  C[M,N] = A[M,K] @ B[N,K]^T, C fp32.
// CTA 128x128, BK=32, 256 threads = 8 warps (4m x 2n), warp tile 32x64.
// ---------------------------------------------------------------------------
__global__ __launch_bounds__(256) void hgemm(const __half* __restrict__ A,
                                             const __half* __restrict__ B,
                                             float* __restrict__ C, int M, int N,
                                             int K) {
    __shared__ __half As[2][128][32];
    __shared__ __half Bs[2][128][32];

    const int tid = threadIdx.x;
    const int wid = tid >> 5;
    const int lane = tid & 31;
    const int wm = wid & 3;
    const int wn = wid >> 2;
    const int r = lane >> 2;
    const int tig = lane & 3;
    const int bx = blockIdx.x;
    const int by = blockIdx.y;

    const __half* Ab = A + (size_t)by * 128 * K;
    const __half* Bb = B + (size_t)bx * 128 * K;

    float acc[2][8][4];
#pragma unroll
    for (int mt = 0; mt < 2; mt++)
#pragma unroll
        for (int nt = 0; nt < 8; nt++)
#pragma unroll
            for (int i = 0; i < 4; i++) acc[mt][nt][i] = 0.0f;

#define LOAD_TILE(buf, k0)                                                         \
    {                                                                              \
        for (int i = 0; i < 2; i++) {                                              \
            int cl = tid + i * 256;                                                \
            int row = cl >> 2;                                                     \
            int c = cl & 3;                                                        \
            int phys = (c ^ ((row >> 1) & 3)) * 8;                                 \
            CPASYNC16(&As[buf][row][phys], Ab + (size_t)row * K + (k0) + c * 8);   \
            CPASYNC16(&Bs[buf][row][phys], Bb + (size_t)row * K + (k0) + c * 8);   \
        }                                                                          \
    }

    LOAD_TILE(0, 0);
    asm volatile("cp.async.commit_group;");

    const int nk = K >> 5;
    for (int kt = 0; kt < nk; kt++) {
        const int buf = kt & 1;
        if (kt + 1 < nk) LOAD_TILE(buf ^ 1, (kt + 1) * 32);
        asm volatile("cp.async.commit_group;");
        asm volatile("cp.async.wait_group 1;");
        __syncthreads();

#pragma unroll
        for (int ks = 0; ks < 2; ks++) {
            const int c0 = ks * 2, c1 = ks * 2 + 1;
            uint32_t a[2][4], b[8][2];
#pragma unroll
            for (int mt = 0; mt < 2; mt++) {
                int r0 = wm * 32 + mt * 16 + r;
                int r1 = r0 + 8;
                int s0 = (r0 >> 1) & 3, s1 = (r1 >> 1) & 3;
                a[mt][0] = *(const uint32_t*)&As[buf][r0][(c0 ^ s0) * 8 + tig * 2];
                a[mt][1] = *(const uint32_t*)&As[buf][r1][(c0 ^ s1) * 8 + tig * 2];
                a[mt][2] = *(const uint32_t*)&As[buf][r0][(c1 ^ s0) * 8 + tig * 2];
                a[mt][3] = *(const uint32_t*)&As[buf][r1][(c1 ^ s1) * 8 + tig * 2];
            }
#pragma unroll
            for (int nt = 0; nt < 8; nt++) {
                int n0 = wn * 64 + nt * 8 + r;
                int sn = (n0 >> 1) & 3;
                b[nt][0] = *(const uint32_t*)&Bs[buf][n0][(c0 ^ sn) * 8 + tig * 2];
                b[nt][1] = *(const uint32_t*)&Bs[buf][n0][(c1 ^ sn) * 8 + tig * 2];
            }
#pragma unroll
            for (int mt = 0; mt < 2; mt++)
#pragma unroll
                for (int nt = 0; nt < 8; nt++)
                    MMA16816(acc[mt][nt], a[mt][0], a[mt][1], a[mt][2], a[mt][3],
                             b[nt][0], b[nt][1]);
        }
        __syncthreads();
    }

#pragma unroll
    for (int mt = 0; mt < 2; mt++) {
        int row = by * 128 + wm * 32 + mt * 16 + r;
#pragma unroll
        for (int nt = 0; nt < 8; nt++) {
            int col = bx * 128 + wn * 64 + nt * 8 + tig * 2;
            *(float2*)&C[(size_t)row * N + col] =
                make_float2(acc[mt][nt][0], acc[mt][nt][1]);
            *(float2*)&C[(size_t)(row + 8) * N + col] =
                make_float2(acc[mt][nt][2], acc[mt][nt][3]);
        }
    }
#undef LOAD_TILE
}

// ---------------------------------------------------------------------------
// fp32 -> fp16 elementwise convert (n divisible by 4)
// ---------------------------------------------------------------------------
__global__ void f32_to_f16(const float* __restrict__ in, __half* __restrict__ out,
                           int n) {
    int i = (blockIdx.x * blockDim.x + threadIdx.x) * 4;
    if (i >= n) return;
    float4 v = *(const float4*)(in + i);
    *(__half2*)(out + i) = __floats2half2_rn(v.x, v.y);
    *(__half2*)(out + i + 2) = __floats2half2_rn(v.z, v.w);
}

// ---------------------------------------------------------------------------
// Transpose + convert: out[C][R] (fp16) = in[R][C] (fp32)
// ---------------------------------------------------------------------------
__global__ void transpose_f16(const float* __restrict__ in, __half* __restrict__ out,
                              int R, int C) {
    __shared__ float t[32][33];
    int bx = blockIdx.x * 32, by = blockIdx.y * 32;
    int x = bx + threadIdx.x;
    for (int i = threadIdx.y; i < 32; i += 8)
        t[i][threadIdx.x] = in[(size_t)(by + i) * C + x];
    __syncthreads();
    int ox = by + threadIdx.x;
    for (int i = threadIdx.y; i < 32; i += 8)
        out[(size_t)(bx + i) * R + ox] = __float2half_rn(t[threadIdx.x][i]);
}

// ---------------------------------------------------------------------------
// RoPE + convert to fp16 head-major: in fp32 [tok][nh*64] -> out [b][h][s][64]
// One thread per (tok, h, pair).  nhp2 = nh*32 (power of 2).
// ---------------------------------------------------------------------------
__global__ void rope_f16(const float* __restrict__ in, const float* __restrict__ fc,
                         const float* __restrict__ fs, __half* __restrict__ out,
                         int nh, int total) {
    int idx = blockIdx.x * blockDim.x + threadIdx.x;
    if (idx >= total) return;
    int per_tok = nh * 32;
    int tok = idx / per_tok;
    int rem = idx - tok * per_tok;
    int h = rem >> 5;
    int j = rem & 31;
    int b = tok >> 11;
    int s = tok & (SEQ - 1);
    const float* p = in + (size_t)tok * (nh * HDIM) + h * HDIM + 2 * j;
    float x1 = p[0], x2 = p[1];
    float c = fc[s * 32 + j], si = fs[s * 32 + j];
    float o1 = x1 * c - x2 * si;
    float o2 = x1 * si + x2 * c;
    *(__half2*)(out + (((size_t)b * nh + h) * SEQ + s) * HDIM + 2 * j) =
        __floats2half2_rn(o1, o2);
}

// ---------------------------------------------------------------------------
// V transpose+convert: fp32 [b*S+s][g*64+d] -> fp16 vt[b][g][d][S]
// grid (S/32, 2, B*NKV), block (32, 8)
// ---------------------------------------------------------------------------
__global__ void v_trans_f16(const float* __restrict__ v, __half* __restrict__ vt) {
    __shared__ float t[32][33];
    int s0 = blockIdx.x * 32, d0 = blockIdx.y * 32;
    int bg = blockIdx.z;
    int b = bg >> 3, g = bg & 7;
    for (int i = threadIdx.y; i < 32; i += 8)
        t[i][threadIdx.x] =
            v[((size_t)b * SEQ + s0 + i) * KVDIM + g * HDIM + d0 + threadIdx.x];
    __syncthreads();
    for (int i = threadIdx.y; i < 32; i += 8)
        vt[((size_t)bg * HDIM + d0 + i) * SEQ + s0 + threadIdx.x] =
            __float2half_rn(t[threadIdx.x][i]);
}

// ---------------------------------------------------------------------------
// Flash attention, fp16 mma.sync, causal, GQA.
// Block: 64 q-rows x 1 head; 128 threads (4 warps x m16).
// Qh [b][h][s][64], Kh [b][g][s][64], Vth [b][g][d][S]; out fp16 [tok][h*64+d].
// ---------------------------------------------------------------------------
__global__ __launch_bounds__(128) void flash_mma(const __half* __restrict__ Qh,
                                                 const __half* __restrict__ Kh,
                                                 const __half* __restrict__ Vth,
                                                 __half* __restrict__ Oh) {
    __shared__ __half Qs[64 * 64];
    __shared__ __half Ks[2][64 * 64];
    __shared__ __half Vs[2][64 * 64];

    const int bq = gridDim.x - 1 - blockIdx.x;  // heavy blocks first
    const int h = blockIdx.y;
    const int b = blockIdx.z;
    const int g = h >> 2;
    const int tid = threadIdx.x;
    const int wid = tid >> 5;
    const int lane = tid & 31;
    const int r = lane >> 2;
    const int tig = lane & 3;
    const int q0 = bq * 64;
    const int rq = wid * 16;
    const int ntile = bq + 1;

    const __half* qbase = Qh + (((size_t)b * NH + h) * SEQ + q0) * HDIM;
    const __half* kbase = Kh + ((size_t)b * NKV + g) * SEQ * HDIM;
    const __half* vbase = Vth + ((size_t)b * NKV + g) * HDIM * SEQ;

    // Prologue: Q + K/V tile 0
#pragma unroll
    for (int i = 0; i < 4; i++) {
        int cl = i * 128 + tid;
        int rr = cl >> 3, cc = cl & 7;
        int ph = rr * 64 + ((cc ^ (rr & 7)) << 3);
        CPASYNC16(&Qs[ph], qbase + rr * HDIM + cc * 8);
        CPASYNC16(&Ks[0][ph], kbase + rr * HDIM + cc * 8);
        CPASYNC16(&Vs[0][ph], vbase + (size_t)rr * SEQ + cc * 8);
    }
    asm volatile("cp.async.commit_group;");

    uint32_t qa[4][4];
    float m0 = -1e30f, m1 = -1e30f, l0 = 0.0f, l1 = 0.0f;
    float acc[8][4];
#pragma unroll
    for (int dt = 0; dt < 8; dt++)
#pragma unroll
        for (int i = 0; i < 4; i++) acc[dt][i] = 0.0f;

    for (int kt = 0; kt < ntile; kt++) {
        if (kt + 1 < ntile) {
            int nb = (kt + 1) & 1;
            const __half* kb = kbase + (size_t)(kt + 1) * 64 * HDIM;
            const __half* vb = vbase + (kt + 1) * 64;
#pragma unroll
            for (int i = 0; i < 4; i++) {
                int cl = i * 128 + tid;
                int rr = cl >> 3, cc = cl & 7;
                int ph = rr * 64 + ((cc ^ (rr & 7)) << 3);
                CPASYNC16(&Ks[nb][ph], kb + rr * HDIM + cc * 8);
                CPASYNC16(&Vs[nb][ph], vb + (size_t)rr * SEQ + cc * 8);
            }
        }
        asm volatile("cp.async.commit_group;");
        asm volatile("cp.async.wait_group 1;");
        __syncthreads();

        if (kt == 0) {  // Q smem ready (loaded with group 0)
#pragma unroll
            for (int kk = 0; kk < 4; kk++) {
                int c = kk * 16 + tig * 2;
                qa[kk][0] = *(const uint32_t*)&Qs[swi(rq + r, c)];
                qa[kk][1] = *(const uint32_t*)&Qs[swi(rq + r + 8, c)];
                qa[kk][2] = *(const uint32_t*)&Qs[swi(rq + r, c + 8)];
                qa[kk][3] = *(const uint32_t*)&Qs[swi(rq + r + 8, c + 8)];
            }
        }

        const __half* ks = Ks[kt & 1];
        const __half* vs = Vs[kt & 1];

        // S = Q K^T (scaled to base-2 domain)
        float s[8][4];
#pragma unroll
        for (int nt = 0; nt < 8; nt++) {
#pragma unroll
            for (int i = 0; i < 4; i++) s[nt][i] = 0.0f;
#pragma unroll
            for (int kk = 0; kk < 4; kk++) {
                uint32_t b0 = *(const uint32_t*)&ks[swi(nt * 8 + r, kk * 16 + tig * 2)];
                uint32_t b1 =
                    *(const uint32_t*)&ks[swi(nt * 8 + r, kk * 16 + 8 + tig * 2)];
                MMA16816(s[nt], qa[kk][0], qa[kk][1], qa[kk][2], qa[kk][3], b0, b1);
            }
        }

        // scale (+ causal mask on diagonal tile)
        if (kt == bq) {
            int row_lo = q0 + rq + r, row_hi = row_lo + 8;
#pragma unroll
            for (int nt = 0; nt < 8; nt++) {
                int col = kt * 64 + nt * 8 + tig * 2;
                s[nt][0] = (col > row_lo) ? -1e30f : s[nt][0] * SCL;
                s[nt][1] = (col + 1 > row_lo) ? -1e30f : s[nt][1] * SCL;
                s[nt][2] = (col > row_hi) ? -1e30f : s[nt][2] * SCL;
                s[nt][3] = (col + 1 > row_hi) ? -1e30f : s[nt][3] * SCL;
            }
        } else {
#pragma unroll
            for (int nt = 0; nt < 8; nt++)
#pragma unroll
                for (int i = 0; i < 4; i++) s[nt][i] *= SCL;
        }

        // online softmax (base-2)
        float mt0 = s[0][0], mt1 = s[0][2];
#pragma unroll
        for (int nt = 0; nt < 8; nt++) {
            mt0 = fmaxf(mt0, fmaxf(s[nt][0], s[nt][1]));
            mt1 = fmaxf(mt1, fmaxf(s[nt][2], s[nt][3]));
        }
        mt0 = fmaxf(mt0, __shfl_xor_sync(0xffffffffu, mt0, 1));
        mt0 = fmaxf(mt0, __shfl_xor_sync(0xffffffffu, mt0, 2));
        mt1 = fmaxf(mt1, __shfl_xor_sync(0xffffffffu, mt1, 1));
        mt1 = fmaxf(mt1, __shfl_xor_sync(0xffffffffu, mt1, 2));
        float mn0 = fmaxf(m0, mt0), mn1 = fmaxf(m1, mt1);
        float rs0 = fast_exp2(m0 - mn0), rs1 = fast_exp2(m1 - mn1);
        m0 = mn0;
        m1 = mn1;

        uint32_t ph[8][2];
        float sum0 = 0.0f, sum1 = 0.0f;
#pragma unroll
        for (int nt = 0; nt < 8; nt++) {
            float p0 = fast_exp2(s[nt][0] - mn0);
            float p1 = fast_exp2(s[nt][1] - mn0);
            float p2 = fast_exp2(s[nt][2] - mn1);
            float p3 = fast_exp2(s[nt][3] - mn1);
            sum0 += p0 + p1;
            sum1 += p2 + p3;
            __half2 h01 = __floats2half2_rn(p0, p1);
            __half2 h23 = __floats2half2_rn(p2, p3);
            ph[nt][0] = *(uint32_t*)&h01;
            ph[nt][1] = *(uint32_t*)&h23;
        }
        sum0 += __shfl_xor_sync(0xffffffffu, sum0, 1);
        sum0 += __shfl_xor_sync(0xffffffffu, sum0, 2);
        sum1 += __shfl_xor_sync(0xffffffffu, sum1, 1);
        sum1 += __shfl_xor_sync(0xffffffffu, sum1, 2);
        l0 = l0 * rs0 + sum0;
        l1 = l1 * rs1 + sum1;

#pragma unroll
        for (int dt = 0; dt < 8; dt++) {
            acc[dt][0] *= rs0;
            acc[dt][1] *= rs0;
            acc[dt][2] *= rs1;
            acc[dt][3] *= rs1;
        }

        // O += P @ V  (Vt stored [d][kv])
#pragma unroll
        for (int dt = 0; dt < 8; dt++) {
#pragma unroll
            for (int kk = 0; kk < 4; kk++) {
                uint32_t b0 = *(const uint32_t*)&vs[swi(dt * 8 + r, kk * 16 + tig * 2)];
                uint32_t b1 =
                    *(const uint32_t*)&vs[swi(dt * 8 + r, kk * 16 + 8 + tig * 2)];
                MMA16816(acc[dt], ph[2 * kk][0], ph[2 * kk][1], ph[2 * kk + 1][0],
                         ph[2 * kk + 1][1], b0, b1);
            }
        }
        __syncthreads();  // done with this buffer before it is refilled
    }

    // normalize + write fp16
    float inv0 = 1.0f / l0, inv1 = 1.0f / l1;
    __half* obase = Oh + ((size_t)b * SEQ + q0 + rq) * QDIM + h * HDIM;
#pragma unroll
    for (int dt = 0; dt < 8; dt++) {
        int col = dt * 8 + tig * 2;
        *(__half2*)(obase + (size_t)r * QDIM + col) =
            __floats2half2_rn(acc[dt][0] * inv0, acc[dt][1] * inv0);
        *(__half2*)(obase + (size_t)(r + 8) * QDIM + col) =
            __floats2half2_rn(acc[dt][2] * inv1, acc[dt][3] * inv1);
    }
}

// ---------------------------------------------------------------------------
// Launch
// ---------------------------------------------------------------------------
extern "C" void kernel_launch(void* const* d_in, const int* in_sizes, int n_in,
                              void* d_out, int out_size) {
    const float* x = (const float*)d_in[0];
    const float* wq = (const float*)d_in[1];
    const float* wk = (const float*)d_in[2];
    const float* wv = (const float*)d_in[3];
    const float* wo = (const float*)d_in[4];
    const float* fc = (const float*)d_in[5];
    const float* fs = (const float*)d_in[6];
    float* out = (float*)d_out;

    float *q, *k, *v;
    __half *xh, *attnh, *qh, *kh, *vth, *wqTh, *wkTh, *wvTh, *woTh;
    cudaGetSymbolAddress((void**)&q, g_q);
    cudaGetSymbolAddress((void**)&k, g_k);
    cudaGetSymbolAddress((void**)&v, g_v);
    cudaGetSymbolAddress((void**)&xh, g_xh);
    cudaGetSymbolAddress((void**)&attnh, g_attnh);
    cudaGetSymbolAddress((void**)&qh, g_qh);
    cudaGetSymbolAddress((void**)&kh, g_kh);
    cudaGetSymbolAddress((void**)&vth, g_vth);
    cudaGetSymbolAddress((void**)&wqTh, g_wqTh);
    cudaGetSymbolAddress((void**)&wkTh, g_wkTh);
    cudaGetSymbolAddress((void**)&wvTh, g_wvTh);
    cudaGetSymbolAddress((void**)&woTh, g_woTh);

    // x -> fp16; weights -> [N][K] fp16
    {
        int n = TOKENS * DMODEL;
        f32_to_f16<<<(n / 4 + 255) / 256, 256>>>(x, xh, n);
    }
    transpose_f16<<<dim3(QDIM / 32, DMODEL / 32), dim3(32, 8)>>>(wq, wqTh, DMODEL,
                                                                 QDIM);
    transpose_f16<<<dim3(KVDIM / 32, DMODEL / 32), dim3(32, 8)>>>(wk, wkTh, DMODEL,
                                                                  KVDIM);
    transpose_f16<<<dim3(KVDIM / 32, DMODEL / 32), dim3(32, 8)>>>(wv, wvTh, DMODEL,
                                                                  KVDIM);
    transpose_f16<<<dim3(DMODEL / 32, QDIM / 32), dim3(32, 8)>>>(wo, woTh, QDIM,
                                                                 DMODEL);

    // QKV projections (fp16 mma, fp32 out)
    hgemm<<<dim3(QDIM / 128, TOKENS / 128), 256>>>(xh, wqTh, q, TOKENS, QDIM, DMODEL);
    hgemm<<<dim3(KVDIM / 128, TOKENS / 128), 256>>>(xh, wkTh, k, TOKENS, KVDIM,
                                                    DMODEL);
    hgemm<<<dim3(KVDIM / 128, TOKENS / 128), 256>>>(xh, wvTh, v, TOKENS, KVDIM,
                                                    DMODEL);

    // RoPE + fp16 head-major conversion; V transpose
    {
        int totq = TOKENS * NH * 32;
        rope_f16<<<(totq + 255) / 256, 256>>>(q, fc, fs, qh, NH, totq);
        int totk = TOKENS * NKV * 32;
        rope_f16<<<(totk + 255) / 256, 256>>>(k, fc, fs, kh, NKV, totk);
        v_trans_f16<<<dim3(SEQ / 32, HDIM / 32, BSZ * NKV), dim3(32, 8)>>>(v, vth);
    }

    // Flash attention (fp16 mma) -> attnh fp16
    flash_mma<<<dim3(SEQ / 64, NH, BSZ), 128>>>(qh, kh, vth, attnh);

    // Output projection
    hgemm<<<dim3(DMODEL / 128, TOKENS / 128), 256>>>(attnh, woTh, out, TOKENS, DMODEL,
                                                     QDIM);
}

// round 9
// speedup vs baseline: 6.1700x; 1.0249x over previous
#include <cuda_runtime.h>
#include <cuda_fp16.h>
#include <cuda_bf16.h>
#include <math.h>
#include <stdint.h>

// Problem dims (fixed)
#define BSZ 2
#define SEQ 2048
#define DMODEL 2048
#define NH 32
#define NKV 8
#define HDIM 64
#define QDIM (NH * HDIM)    // 2048
#define KVDIM (NKV * HDIM)  // 512
#define TOKENS (BSZ * SEQ)  // 4096

// scale = 1/sqrt(64) * log2(e)
#define SCL 0.1803368801111204f

// Scratch (static device globals; allocation is forbidden)
__device__ __half g_xh[(size_t)TOKENS * DMODEL];
__device__ __half g_attnh[(size_t)TOKENS * QDIM];
__device__ __half g_qh[(size_t)TOKENS * QDIM];    // [B][NH][S][64]
__device__ __half g_kh[(size_t)TOKENS * KVDIM];   // [B][NKV][S][64]
__device__ __half g_vth[(size_t)TOKENS * KVDIM];  // [B][NKV][64][S]
__device__ __half g_wqTh[(size_t)QDIM * DMODEL];  // [N][K]
__device__ __half g_wkTh[(size_t)KVDIM * DMODEL];
__device__ __half g_wvTh[(size_t)KVDIM * DMODEL];
__device__ __half g_woTh[(size_t)DMODEL * QDIM];

#define MMA16816(d, a0, a1, a2, a3, b0, b1)                      \
    asm volatile(                                                \
        "mma.sync.aligned.m16n8k16.row.col.f32.f16.f16.f32 "     \
        "{%0,%1,%2,%3}, {%4,%5,%6,%7}, {%8,%9}, {%0,%1,%2,%3};"  \
        : "+f"((d)[0]), "+f"((d)[1]), "+f"((d)[2]), "+f"((d)[3]) \
        : "r"(a0), "r"(a1), "r"(a2), "r"(a3), "r"(b0), "r"(b1))

#define CPASYNC16(smem_half_ptr, gptr)                                   \
    asm volatile("cp.async.cg.shared.global [%0], [%1], 16;" ::"r"(      \
                     (uint32_t)__cvta_generic_to_shared(smem_half_ptr)), \
                 "l"(gptr))

// exp2 on FMA/ALU pipes (x <= 0 expected; clamped to >= -126)
__device__ __forceinline__ float fast_exp2(float x) {
    x = fmaxf(x, -126.0f);
    float z = x + 12582912.0f;  // 1.5 * 2^23
    int n = __float_as_int(z) << 23;
    float f = x - (z - 12582912.0f);  // f in [-0.5, 0.5]
    float y = 0.0013276471f;
    y = fmaf(y, f, 0.0096181993f);
    y = fmaf(y, f, 0.0555041086f);
    y = fmaf(y, f, 0.2402264923f);
    y = fmaf(y, f, 0.6931471825f);
    y = fmaf(y, f, 1.0f);
    return __int_as_float(__float_as_int(y) + n);
}

// swizzled index of half element (r, c) in a [64][64] tile
__device__ __forceinline__ int swi(int r, int c) {
    return r * 64 + ((((c >> 3) ^ (r & 7)) << 3) + (c & 7));
}

// ---------------------------------------------------------------------------
// hgemm3<MODE>: C = A[M,K] @ B[N,K]^T, fp16 in, fp32 accum.
// Round-5-proven inner loop: CTA 128x128, BK=32, 2-stage cp.async,
// 256 thr = 8 warps (4m x 2n), scalar LDS fragment loads, static smem.
// Epilogue:
//   MODE 0: fp32 C[M,N]
//   MODE 1: RoPE + fp16 head-major [b][h][s][64]  (nh heads)
//   MODE 3: fp16 transposed head-major [b][h][d][S]  (nh heads)
// ---------------------------------------------------------------------------
template <int MODE>
__global__ __launch_bounds__(256) void hgemm3(const __half* __restrict__ A,
                                              const __half* __restrict__ B,
                                              void* __restrict__ Cout,
                                              const float* __restrict__ fc,
                                              const float* __restrict__ fs, int M,
                                              int N, int K, int nh) {
    __shared__ __half As[2][128][32];
    __shared__ __half Bs[2][128][32];

    const int tid = threadIdx.x;
    const int wid = tid >> 5;
    const int lane = tid & 31;
    const int wm = wid & 3;
    const int wn = wid >> 2;
    const int r = lane >> 2;
    const int tig = lane & 3;
    const int bx = blockIdx.x;
    const int by = blockIdx.y;

    const __half* Ab = A + (size_t)by * 128 * K;
    const __half* Bb = B + (size_t)bx * 128 * K;

    float acc[2][8][4];
#pragma unroll
    for (int mt = 0; mt < 2; mt++)
#pragma unroll
        for (int nt = 0; nt < 8; nt++)
#pragma unroll
            for (int i = 0; i < 4; i++) acc[mt][nt][i] = 0.0f;

#define LOAD_TILE(buf, k0)                                                       \
    {                                                                            \
        for (int i = 0; i < 2; i++) {                                            \
            int cl = tid + i * 256;                                              \
            int row = cl >> 2;                                                   \
            int c = cl & 3;                                                      \
            int phys = (c ^ ((row >> 1) & 3)) * 8;                               \
            CPASYNC16(&As[buf][row][phys], Ab + (size_t)row * K + (k0) + c * 8); \
            CPASYNC16(&Bs[buf][row][phys], Bb + (size_t)row * K + (k0) + c * 8); \
        }                                                                        \
    }

    LOAD_TILE(0, 0);
    asm volatile("cp.async.commit_group;");

    const int nk = K >> 5;
    for (int kt = 0; kt < nk; kt++) {
        const int buf = kt & 1;
        if (kt + 1 < nk) LOAD_TILE(buf ^ 1, (kt + 1) * 32);
        asm volatile("cp.async.commit_group;");
        asm volatile("cp.async.wait_group 1;");
        __syncthreads();

#pragma unroll
        for (int ks = 0; ks < 2; ks++) {
            const int c0 = ks * 2, c1 = ks * 2 + 1;
            uint32_t a[2][4], b[8][2];
#pragma unroll
            for (int mt = 0; mt < 2; mt++) {
                int r0 = wm * 32 + mt * 16 + r;
                int r1 = r0 + 8;
                int s0 = (r0 >> 1) & 3, s1 = (r1 >> 1) & 3;
                a[mt][0] = *(const uint32_t*)&As[buf][r0][(c0 ^ s0) * 8 + tig * 2];
                a[mt][1] = *(const uint32_t*)&As[buf][r1][(c0 ^ s1) * 8 + tig * 2];
                a[mt][2] = *(const uint32_t*)&As[buf][r0][(c1 ^ s0) * 8 + tig * 2];
                a[mt][3] = *(const uint32_t*)&As[buf][r1][(c1 ^ s1) * 8 + tig * 2];
            }
#pragma unroll
            for (int nt = 0; nt < 8; nt++) {
                int n0 = wn * 64 + nt * 8 + r;
                int sn = (n0 >> 1) & 3;
                b[nt][0] = *(const uint32_t*)&Bs[buf][n0][(c0 ^ sn) * 8 + tig * 2];
                b[nt][1] = *(const uint32_t*)&Bs[buf][n0][(c1 ^ sn) * 8 + tig * 2];
            }
#pragma unroll
            for (int mt = 0; mt < 2; mt++)
#pragma unroll
                for (int nt = 0; nt < 8; nt++)
                    MMA16816(acc[mt][nt], a[mt][0], a[mt][1], a[mt][2], a[mt][3],
                             b[nt][0], b[nt][1]);
        }
        __syncthreads();
    }

    // Epilogue
#pragma unroll
    for (int mt = 0; mt < 2; mt++) {
        int row = by * 128 + wm * 32 + mt * 16 + r;  // rows row, row+8
#pragma unroll
        for (int nt = 0; nt < 8; nt++) {
            int col = bx * 128 + wn * 64 + nt * 8 + tig * 2;
            if (MODE == 0) {
                float* C = (float*)Cout;
                *(float2*)&C[(size_t)row * N + col] =
                    make_float2(acc[mt][nt][0], acc[mt][nt][1]);
                *(float2*)&C[(size_t)(row + 8) * N + col] =
                    make_float2(acc[mt][nt][2], acc[mt][nt][3]);
            } else if (MODE == 1) {
                __half* O = (__half*)Cout;
                int b = row >> 11;
                int s = row & (SEQ - 1);
                int h = col >> 6;
                int d = col & 63;
                int j = d >> 1;
                __half* dst = O + (((size_t)b * nh + h) * SEQ + s) * HDIM + d;
                float c0v = fc[s * 32 + j], s0v = fs[s * 32 + j];
                float c1v = fc[(s + 8) * 32 + j], s1v = fs[(s + 8) * 32 + j];
                *(__half2*)dst =
                    __floats2half2_rn(acc[mt][nt][0] * c0v - acc[mt][nt][1] * s0v,
                                      acc[mt][nt][0] * s0v + acc[mt][nt][1] * c0v);
                *(__half2*)(dst + 8 * HDIM) =
                    __floats2half2_rn(acc[mt][nt][2] * c1v - acc[mt][nt][3] * s1v,
                                      acc[mt][nt][2] * s1v + acc[mt][nt][3] * c1v);
            } else {  // MODE 3: transposed [b][h][d][S]
                __half* O = (__half*)Cout;
                int b = row >> 11;
                int s = row & (SEQ - 1);
                int h = col >> 6;
                int d = col & 63;
                __half* dst = O + (((size_t)b * nh + h) * HDIM + d) * SEQ + s;
                dst[0] = __float2half_rn(acc[mt][nt][0]);
                dst[SEQ] = __float2half_rn(acc[mt][nt][1]);
                dst[8] = __float2half_rn(acc[mt][nt][2]);
                dst[SEQ + 8] = __float2half_rn(acc[mt][nt][3]);
            }
        }
    }
#undef LOAD_TILE
}

// ---------------------------------------------------------------------------
// fp32 -> fp16 elementwise convert (n divisible by 4)
// ---------------------------------------------------------------------------
__global__ void f32_to_f16(const float* __restrict__ in, __half* __restrict__ out,
                           int n) {
    int i = (blockIdx.x * blockDim.x + threadIdx.x) * 4;
    if (i >= n) return;
    float4 v = *(const float4*)(in + i);
    *(__half2*)(out + i) = __floats2half2_rn(v.x, v.y);
    *(__half2*)(out + i + 2) = __floats2half2_rn(v.z, v.w);
}

// ---------------------------------------------------------------------------
// Transpose + convert: out[C][R] (fp16) = in[R][C] (fp32)
// ---------------------------------------------------------------------------
__global__ void transpose_f16(const float* __restrict__ in, __half* __restrict__ out,
                              int R, int C) {
    __shared__ float t[32][33];
    int bx = blockIdx.x * 32, by = blockIdx.y * 32;
    int x = bx + threadIdx.x;
    for (int i = threadIdx.y; i < 32; i += 8)
        t[i][threadIdx.x] = in[(size_t)(by + i) * C + x];
    __syncthreads();
    int ox = by + threadIdx.x;
    for (int i = threadIdx.y; i < 32; i += 8)
        out[(size_t)(bx + i) * R + ox] = __float2half_rn(t[threadIdx.x][i]);
}

// ---------------------------------------------------------------------------
// Flash attention, fp16 mma.sync, causal, GQA (round-5 proven, verbatim).
// Block: 64 q-rows x 1 head; 128 threads (4 warps x m16).
// Qh [b][h][s][64], Kh [b][g][s][64], Vth [b][g][d][S]; out fp16 [tok][h*64+d].
// ---------------------------------------------------------------------------
__global__ __launch_bounds__(128) void flash_mma(const __half* __restrict__ Qh,
                                                 const __half* __restrict__ Kh,
                                                 const __half* __restrict__ Vth,
                                                 __half* __restrict__ Oh) {
    __shared__ __half Qs[64 * 64];
    __shared__ __half Ks[2][64 * 64];
    __shared__ __half Vs[2][64 * 64];

    const int bq = gridDim.x - 1 - blockIdx.x;  // heavy blocks first
    const int h = blockIdx.y;
    const int b = blockIdx.z;
    const int g = h >> 2;
    const int tid = threadIdx.x;
    const int wid = tid >> 5;
    const int lane = tid & 31;
    const int r = lane >> 2;
    const int tig = lane & 3;
    const int q0 = bq * 64;
    const int rq = wid * 16;
    const int ntile = bq + 1;

    const __half* qbase = Qh + (((size_t)b * NH + h) * SEQ + q0) * HDIM;
    const __half* kbase = Kh + ((size_t)b * NKV + g) * SEQ * HDIM;
    const __half* vbase = Vth + ((size_t)b * NKV + g) * HDIM * SEQ;

    // Prologue: Q + K/V tile 0
#pragma unroll
    for (int i = 0; i < 4; i++) {
        int cl = i * 128 + tid;
        int rr = cl >> 3, cc = cl & 7;
        int ph = rr * 64 + ((cc ^ (rr & 7)) << 3);
        CPASYNC16(&Qs[ph], qbase + rr * HDIM + cc * 8);
        CPASYNC16(&Ks[0][ph], kbase + rr * HDIM + cc * 8);
        CPASYNC16(&Vs[0][ph], vbase + (size_t)rr * SEQ + cc * 8);
    }
    asm volatile("cp.async.commit_group;");

    uint32_t qa[4][4];
    float m0 = -1e30f, m1 = -1e30f, l0 = 0.0f, l1 = 0.0f;
    float acc[8][4];
#pragma unroll
    for (int dt = 0; dt < 8; dt++)
#pragma unroll
        for (int i = 0; i < 4; i++) acc[dt][i] = 0.0f;

    for (int kt = 0; kt < ntile; kt++) {
        if (kt + 1 < ntile) {
            int nb = (kt + 1) & 1;
            const __half* kb = kbase + (size_t)(kt + 1) * 64 * HDIM;
            const __half* vb = vbase + (kt + 1) * 64;
#pragma unroll
            for (int i = 0; i < 4; i++) {
                int cl = i * 128 + tid;
                int rr = cl >> 3, cc = cl & 7;
                int ph = rr * 64 + ((cc ^ (rr & 7)) << 3);
                CPASYNC16(&Ks[nb][ph], kb + rr * HDIM + cc * 8);
                CPASYNC16(&Vs[nb][ph], vb + (size_t)rr * SEQ + cc * 8);
            }
        }
        asm volatile("cp.async.commit_group;");
        asm volatile("cp.async.wait_group 1;");
        __syncthreads();

        if (kt == 0) {  // Q smem ready (loaded with group 0)
#pragma unroll
            for (int kk = 0; kk < 4; kk++) {
                int c = kk * 16 + tig * 2;
                qa[kk][0] = *(const uint32_t*)&Qs[swi(rq + r, c)];
                qa[kk][1] = *(const uint32_t*)&Qs[swi(rq + r + 8, c)];
                qa[kk][2] = *(const uint32_t*)&Qs[swi(rq + r, c + 8)];
                qa[kk][3] = *(const uint32_t*)&Qs[swi(rq + r + 8, c + 8)];
            }
        }

        const __half* ks = Ks[kt & 1];
        const __half* vs = Vs[kt & 1];

        // S = Q K^T
        float s[8][4];
#pragma unroll
        for (int nt = 0; nt < 8; nt++) {
#pragma unroll
            for (int i = 0; i < 4; i++) s[nt][i] = 0.0f;
#pragma unroll
            for (int kk = 0; kk < 4; kk++) {
                uint32_t b0 = *(const uint32_t*)&ks[swi(nt * 8 + r, kk * 16 + tig * 2)];
                uint32_t b1 =
                    *(const uint32_t*)&ks[swi(nt * 8 + r, kk * 16 + 8 + tig * 2)];
                MMA16816(s[nt], qa[kk][0], qa[kk][1], qa[kk][2], qa[kk][3], b0, b1);
            }
        }

        // scale (+ causal mask on diagonal tile)
        if (kt == bq) {
            int row_lo = q0 + rq + r, row_hi = row_lo + 8;
#pragma unroll
            for (int nt = 0; nt < 8; nt++) {
                int col = kt * 64 + nt * 8 + tig * 2;
                s[nt][0] = (col > row_lo) ? -1e30f : s[nt][0] * SCL;
                s[nt][1] = (col + 1 > row_lo) ? -1e30f : s[nt][1] * SCL;
                s[nt][2] = (col > row_hi) ? -1e30f : s[nt][2] * SCL;
                s[nt][3] = (col + 1 > row_hi) ? -1e30f : s[nt][3] * SCL;
            }
        } else {
#pragma unroll
            for (int nt = 0; nt < 8; nt++)
#pragma unroll
                for (int i = 0; i < 4; i++) s[nt][i] *= SCL;
        }

        // online softmax (base-2)
        float mt0 = s[0][0], mt1 = s[0][2];
#pragma unroll
        for (int nt = 0; nt < 8; nt++) {
            mt0 = fmaxf(mt0, fmaxf(s[nt][0], s[nt][1]));
            mt1 = fmaxf(mt1, fmaxf(s[nt][2], s[nt][3]));
        }
        mt0 = fmaxf(mt0, __shfl_xor_sync(0xffffffffu, mt0, 1));
        mt0 = fmaxf(mt0, __shfl_xor_sync(0xffffffffu, mt0, 2));
        mt1 = fmaxf(mt1, __shfl_xor_sync(0xffffffffu, mt1, 1));
        mt1 = fmaxf(mt1, __shfl_xor_sync(0xffffffffu, mt1, 2));
        float mn0 = fmaxf(m0, mt0), mn1 = fmaxf(m1, mt1);
        float rs0 = fast_exp2(m0 - mn0), rs1 = fast_exp2(m1 - mn1);
        m0 = mn0;
        m1 = mn1;

        uint32_t ph[8][2];
        float sum0 = 0.0f, sum1 = 0.0f;
#pragma unroll
        for (int nt = 0; nt < 8; nt++) {
            float p0 = fast_exp2(s[nt][0] - mn0);
            float p1 = fast_exp2(s[nt][1] - mn0);
            float p2 = fast_exp2(s[nt][2] - mn1);
            float p3 = fast_exp2(s[nt][3] - mn1);
            sum0 += p0 + p1;
            sum1 += p2 + p3;
            __half2 h01 = __floats2half2_rn(p0, p1);
            __half2 h23 = __floats2half2_rn(p2, p3);
            ph[nt][0] = *(uint32_t*)&h01;
            ph[nt][1] = *(uint32_t*)&h23;
        }
        sum0 += __shfl_xor_sync(0xffffffffu, sum0, 1);
        sum0 += __shfl_xor_sync(0xffffffffu, sum0, 2);
        sum1 += __shfl_xor_sync(0xffffffffu, sum1, 1);
        sum1 += __shfl_xor_sync(0xffffffffu, sum1, 2);
        l0 = l0 * rs0 + sum0;
        l1 = l1 * rs1 + sum1;

#pragma unroll
        for (int dt = 0; dt < 8; dt++) {
            acc[dt][0] *= rs0;
            acc[dt][1] *= rs0;
            acc[dt][2] *= rs1;
            acc[dt][3] *= rs1;
        }

        // O += P @ V  (Vt stored [d][kv])
#pragma unroll
        for (int dt = 0; dt < 8; dt++) {
#pragma unroll
            for (int kk = 0; kk < 4; kk++) {
                uint32_t b0 = *(const uint32_t*)&vs[swi(dt * 8 + r, kk * 16 + tig * 2)];
                uint32_t b1 =
                    *(const uint32_t*)&vs[swi(dt * 8 + r, kk * 16 + 8 + tig * 2)];
                MMA16816(acc[dt], ph[2 * kk][0], ph[2 * kk][1], ph[2 * kk + 1][0],
                         ph[2 * kk + 1][1], b0, b1);
            }
        }
        __syncthreads();  // done with this buffer before it is refilled
    }

    // normalize + write fp16
    float inv0 = 1.0f / l0, inv1 = 1.0f / l1;
    __half* obase = Oh + ((size_t)b * SEQ + q0 + rq) * QDIM + h * HDIM;
#pragma unroll
    for (int dt = 0; dt < 8; dt++) {
        int col = dt * 8 + tig * 2;
        *(__half2*)(obase + (size_t)r * QDIM + col) =
            __floats2half2_rn(acc[dt][0] * inv0, acc[dt][1] * inv0);
        *(__half2*)(obase + (size_t)(r + 8) * QDIM + col) =
            __floats2half2_rn(acc[dt][2] * inv1, acc[dt][3] * inv1);
    }
}

// ---------------------------------------------------------------------------
// Launch
// ---------------------------------------------------------------------------
extern "C" void kernel_launch(void* const* d_in, const int* in_sizes, int n_in,
                              void* d_out, int out_size) {
    const float* x = (const float*)d_in[0];
    const float* wq = (const float*)d_in[1];
    const float* wk = (const float*)d_in[2];
    const float* wv = (const float*)d_in[3];
    const float* wo = (const float*)d_in[4];
    const float* fc = (const float*)d_in[5];
    const float* fs = (const float*)d_in[6];
    float* out = (float*)d_out;

    __half *xh, *attnh, *qh, *kh, *vth, *wqTh, *wkTh, *wvTh, *woTh;
    cudaGetSymbolAddress((void**)&xh, g_xh);
    cudaGetSymbolAddress((void**)&attnh, g_attnh);
    cudaGetSymbolAddress((void**)&qh, g_qh);
    cudaGetSymbolAddress((void**)&kh, g_kh);
    cudaGetSymbolAddress((void**)&vth, g_vth);
    cudaGetSymbolAddress((void**)&wqTh, g_wqTh);
    cudaGetSymbolAddress((void**)&wkTh, g_wkTh);
    cudaGetSymbolAddress((void**)&wvTh, g_wvTh);
    cudaGetSymbolAddress((void**)&woTh, g_woTh);

    // x -> fp16; weights -> [N][K] fp16
    {
        int n = TOKENS * DMODEL;
        f32_to_f16<<<(n / 4 + 255) / 256, 256>>>(x, xh, n);
    }
    transpose_f16<<<dim3(QDIM / 32, DMODEL / 32), dim3(32, 8)>>>(wq, wqTh, DMODEL,
                                                                 QDIM);
    transpose_f16<<<dim3(KVDIM / 32, DMODEL / 32), dim3(32, 8)>>>(wk, wkTh, DMODEL,
                                                                  KVDIM);
    transpose_f16<<<dim3(KVDIM / 32, DMODEL / 32), dim3(32, 8)>>>(wv, wvTh, DMODEL,
                                                                  KVDIM);
    transpose_f16<<<dim3(DMODEL / 32, QDIM / 32), dim3(32, 8)>>>(wo, woTh, QDIM,
                                                                 DMODEL);

    // Q/K projections with fused RoPE -> fp16 head-major;
    // V projection -> fp16 transposed head-major [b][g][d][S]
    hgemm3<1><<<dim3(QDIM / 128, TOKENS / 128), 256>>>(xh, wqTh, qh, fc, fs, TOKENS,
                                                       QDIM, DMODEL, NH);
    hgemm3<1><<<dim3(KVDIM / 128, TOKENS / 128), 256>>>(xh, wkTh, kh, fc, fs, TOKENS,
                                                        KVDIM, DMODEL, NKV);
    hgemm3<3><<<dim3(KVDIM / 128, TOKENS / 128), 256>>>(xh, wvTh, vth, fc, fs, TOKENS,
                                                        KVDIM, DMODEL, NKV);

    // Flash attention (fp16 mma) -> attnh fp16
    flash_mma<<<dim3(SEQ / 64, NH, BSZ), 128>>>(qh, kh, vth, attnh);

    // Output projection -> fp32 out
    hgemm3<0><<<dim3(DMODEL / 128, TOKENS / 128), 256>>>(attnh, woTh, out, fc, fs,
                                                         TOKENS, DMODEL, QDIM, 1);
}

// round 11
// speedup vs baseline: 6.4684x; 1.0484x over previous
#include <cuda_runtime.h>
#include <cuda_fp16.h>
#include <cuda_bf16.h>
#include <math.h>
#include <stdint.h>

// Problem dims (fixed)
#define BSZ 2
#define SEQ 2048
#define DMODEL 2048
#define NH 32
#define NKV 8
#define HDIM 64
#define QDIM (NH * HDIM)    // 2048
#define KVDIM (NKV * HDIM)  // 512
#define TOKENS (BSZ * SEQ)  // 4096
#define NQKV (QDIM + 2 * KVDIM)  // 3072

// scale = 1/sqrt(64) * log2(e)
#define SCL 0.1803368801111204f

// Scratch (static device globals; allocation is forbidden)
__device__ __half g_xh[(size_t)TOKENS * DMODEL];
__device__ __half g_attnh[(size_t)TOKENS * QDIM];
__device__ __half g_qh[(size_t)TOKENS * QDIM];    // [B][NH][S][64]
__device__ __half g_kh[(size_t)TOKENS * KVDIM];   // [B][NKV][S][64]
__device__ __half g_vth[(size_t)TOKENS * KVDIM];  // [B][NKV][64][S]
__device__ __half g_wqkvTh[(size_t)NQKV * DMODEL];  // [3072][2048] = wqT|wkT|wvT
__device__ __half g_woTh[(size_t)DMODEL * QDIM];

#define MMA16816(d, a0, a1, a2, a3, b0, b1)                      \
    asm volatile(                                                \
        "mma.sync.aligned.m16n8k16.row.col.f32.f16.f16.f32 "     \
        "{%0,%1,%2,%3}, {%4,%5,%6,%7}, {%8,%9}, {%0,%1,%2,%3};"  \
        : "+f"((d)[0]), "+f"((d)[1]), "+f"((d)[2]), "+f"((d)[3]) \
        : "r"(a0), "r"(a1), "r"(a2), "r"(a3), "r"(b0), "r"(b1))

#define CPASYNC16(smem_half_ptr, gptr)                                   \
    asm volatile("cp.async.cg.shared.global [%0], [%1], 16;" ::"r"(      \
                     (uint32_t)__cvta_generic_to_shared(smem_half_ptr)), \
                 "l"(gptr))

// exp2 on FMA/ALU pipes (x <= 0 expected; clamped to >= -126)
__device__ __forceinline__ float fast_exp2(float x) {
    x = fmaxf(x, -126.0f);
    float z = x + 12582912.0f;  // 1.5 * 2^23
    int n = __float_as_int(z) << 23;
    float f = x - (z - 12582912.0f);  // f in [-0.5, 0.5]
    float y = 0.0013276471f;
    y = fmaf(y, f, 0.0096181993f);
    y = fmaf(y, f, 0.0555041086f);
    y = fmaf(y, f, 0.2402264923f);
    y = fmaf(y, f, 0.6931471825f);
    y = fmaf(y, f, 1.0f);
    return __int_as_float(__float_as_int(y) + n);
}

// swizzled index of half element (r, c) in a [64][64] tile
__device__ __forceinline__ int swi(int r, int c) {
    return r * 64 + ((((c >> 3) ^ (r & 7)) << 3) + (c & 7));
}

// ---------------------------------------------------------------------------
// hgemm3<MODE>: C = A[M,K] @ B[N,K]^T, fp16 in, fp32 accum.
// Round-9-proven inner loop: CTA 128x128, BK=32, 2-stage cp.async,
// 256 thr = 8 warps (4m x 2n), scalar LDS fragment loads, static smem.
// Epilogue:
//   MODE 0: fp32 C0[M,N]
//   MODE 4: fused QKV routing by column region:
//     col <  2048        : RoPE + fp16 head-major -> C0 (qh, NH heads)
//     2048 <= col < 2560 : RoPE + fp16 head-major -> C1 (kh, NKV heads)
//     col >= 2560        : fp16 transposed head-major -> C2 (vth, NKV heads)
// ---------------------------------------------------------------------------
template <int MODE>
__global__ __launch_bounds__(256) void hgemm3(const __half* __restrict__ A,
                                              const __half* __restrict__ B,
                                              void* __restrict__ C0,
                                              __half* __restrict__ C1,
                                              __half* __restrict__ C2,
                                              const float* __restrict__ fc,
                                              const float* __restrict__ fs, int M,
                                              int N, int K) {
    __shared__ __half As[2][128][32];
    __shared__ __half Bs[2][128][32];

    const int tid = threadIdx.x;
    const int wid = tid >> 5;
    const int lane = tid & 31;
    const int wm = wid & 3;
    const int wn = wid >> 2;
    const int r = lane >> 2;
    const int tig = lane & 3;
    const int bx = blockIdx.x;
    const int by = blockIdx.y;

    const __half* Ab = A + (size_t)by * 128 * K;
    const __half* Bb = B + (size_t)bx * 128 * K;

    float acc[2][8][4];
#pragma unroll
    for (int mt = 0; mt < 2; mt++)
#pragma unroll
        for (int nt = 0; nt < 8; nt++)
#pragma unroll
            for (int i = 0; i < 4; i++) acc[mt][nt][i] = 0.0f;

#define LOAD_TILE(buf, k0)                                                       \
    {                                                                            \
        for (int i = 0; i < 2; i++) {                                            \
            int cl = tid + i * 256;                                              \
            int row = cl >> 2;                                                   \
            int c = cl & 3;                                                      \
            int phys = (c ^ ((row >> 1) & 3)) * 8;                               \
            CPASYNC16(&As[buf][row][phys], Ab + (size_t)row * K + (k0) + c * 8); \
            CPASYNC16(&Bs[buf][row][phys], Bb + (size_t)row * K + (k0) + c * 8); \
        }                                                                        \
    }

    LOAD_TILE(0, 0);
    asm volatile("cp.async.commit_group;");

    const int nk = K >> 5;
    for (int kt = 0; kt < nk; kt++) {
        const int buf = kt & 1;
        if (kt + 1 < nk) LOAD_TILE(buf ^ 1, (kt + 1) * 32);
        asm volatile("cp.async.commit_group;");
        asm volatile("cp.async.wait_group 1;");
        __syncthreads();

#pragma unroll
        for (int ks = 0; ks < 2; ks++) {
            const int c0 = ks * 2, c1 = ks * 2 + 1;
            uint32_t a[2][4], b[8][2];
#pragma unroll
            for (int mt = 0; mt < 2; mt++) {
                int r0 = wm * 32 + mt * 16 + r;
                int r1 = r0 + 8;
                int s0 = (r0 >> 1) & 3, s1 = (r1 >> 1) & 3;
                a[mt][0] = *(const uint32_t*)&As[buf][r0][(c0 ^ s0) * 8 + tig * 2];
                a[mt][1] = *(const uint32_t*)&As[buf][r1][(c0 ^ s1) * 8 + tig * 2];
                a[mt][2] = *(const uint32_t*)&As[buf][r0][(c1 ^ s0) * 8 + tig * 2];
                a[mt][3] = *(const uint32_t*)&As[buf][r1][(c1 ^ s1) * 8 + tig * 2];
            }
#pragma unroll
            for (int nt = 0; nt < 8; nt++) {
                int n0 = wn * 64 + nt * 8 + r;
                int sn = (n0 >> 1) & 3;
                b[nt][0] = *(const uint32_t*)&Bs[buf][n0][(c0 ^ sn) * 8 + tig * 2];
                b[nt][1] = *(const uint32_t*)&Bs[buf][n0][(c1 ^ sn) * 8 + tig * 2];
            }
#pragma unroll
            for (int mt = 0; mt < 2; mt++)
#pragma unroll
                for (int nt = 0; nt < 8; nt++)
                    MMA16816(acc[mt][nt], a[mt][0], a[mt][1], a[mt][2], a[mt][3],
                             b[nt][0], b[nt][1]);
        }
        __syncthreads();
    }

    // Epilogue
#pragma unroll
    for (int mt = 0; mt < 2; mt++) {
        int row = by * 128 + wm * 32 + mt * 16 + r;  // rows row, row+8
#pragma unroll
        for (int nt = 0; nt < 8; nt++) {
            int col = bx * 128 + wn * 64 + nt * 8 + tig * 2;
            if (MODE == 0) {
                float* C = (float*)C0;
                *(float2*)&C[(size_t)row * N + col] =
                    make_float2(acc[mt][nt][0], acc[mt][nt][1]);
                *(float2*)&C[(size_t)(row + 8) * N + col] =
                    make_float2(acc[mt][nt][2], acc[mt][nt][3]);
            } else {  // MODE 4: fused QKV routing
                int b = row >> 11;
                int s = row & (SEQ - 1);
                if (col < QDIM + KVDIM) {
                    // Q or K: RoPE + head-major
                    __half* base;
                    int c2, nheads;
                    if (col < QDIM) {
                        base = (__half*)C0;
                        c2 = col;
                        nheads = NH;
                    } else {
                        base = C1;
                        c2 = col - QDIM;
                        nheads = NKV;
                    }
                    int h = c2 >> 6;
                    int d = c2 & 63;
                    int j = d >> 1;
                    __half* dst =
                        base + (((size_t)b * nheads + h) * SEQ + s) * HDIM + d;
                    float c0v = fc[s * 32 + j], s0v = fs[s * 32 + j];
                    float c1v = fc[(s + 8) * 32 + j], s1v = fs[(s + 8) * 32 + j];
                    *(__half2*)dst = __floats2half2_rn(
                        acc[mt][nt][0] * c0v - acc[mt][nt][1] * s0v,
                        acc[mt][nt][0] * s0v + acc[mt][nt][1] * c0v);
                    *(__half2*)(dst + 8 * HDIM) = __floats2half2_rn(
                        acc[mt][nt][2] * c1v - acc[mt][nt][3] * s1v,
                        acc[mt][nt][2] * s1v + acc[mt][nt][3] * c1v);
                } else {
                    // V: transposed head-major [b][g][d][S]
                    int c2 = col - QDIM - KVDIM;
                    int h = c2 >> 6;
                    int d = c2 & 63;
                    __half* dst = C2 + (((size_t)b * NKV + h) * HDIM + d) * SEQ + s;
                    dst[0] = __float2half_rn(acc[mt][nt][0]);
                    dst[SEQ] = __float2half_rn(acc[mt][nt][1]);
                    dst[8] = __float2half_rn(acc[mt][nt][2]);
                    dst[SEQ + 8] = __float2half_rn(acc[mt][nt][3]);
                }
            }
        }
    }
#undef LOAD_TILE
}

// ---------------------------------------------------------------------------
// fp32 -> fp16 elementwise convert (n divisible by 4)
// ---------------------------------------------------------------------------
__global__ void f32_to_f16(const float* __restrict__ in, __half* __restrict__ out,
                           int n) {
    int i = (blockIdx.x * blockDim.x + threadIdx.x) * 4;
    if (i >= n) return;
    float4 v = *(const float4*)(in + i);
    *(__half2*)(out + i) = __floats2half2_rn(v.x, v.y);
    *(__half2*)(out + i + 2) = __floats2half2_rn(v.z, v.w);
}

// ---------------------------------------------------------------------------
// Transpose + convert: out[C][R] (fp16) = in[R][C] (fp32)
// out has row stride R (caller may pass a slice of a larger [*, R] buffer).
// ---------------------------------------------------------------------------
__global__ void transpose_f16(const float* __restrict__ in, __half* __restrict__ out,
                              int R, int C) {
    __shared__ float t[32][33];
    int bx = blockIdx.x * 32, by = blockIdx.y * 32;
    int x = bx + threadIdx.x;
    for (int i = threadIdx.y; i < 32; i += 8)
        t[i][threadIdx.x] = in[(size_t)(by + i) * C + x];
    __syncthreads();
    int ox = by + threadIdx.x;
    for (int i = threadIdx.y; i < 32; i += 8)
        out[(size_t)(bx + i) * R + ox] = __float2half_rn(t[threadIdx.x][i]);
}

// ---------------------------------------------------------------------------
// Flash attention, fp16 mma.sync, causal, GQA (round-5/9 proven, verbatim).
// Block: 64 q-rows x 1 head; 128 threads (4 warps x m16).
// Qh [b][h][s][64], Kh [b][g][s][64], Vth [b][g][d][S]; out fp16 [tok][h*64+d].
// ---------------------------------------------------------------------------
__global__ __launch_bounds__(128) void flash_mma(const __half* __restrict__ Qh,
                                                 const __half* __restrict__ Kh,
                                                 const __half* __restrict__ Vth,
                                                 __half* __restrict__ Oh) {
    __shared__ __half Qs[64 * 64];
    __shared__ __half Ks[2][64 * 64];
    __shared__ __half Vs[2][64 * 64];

    const int bq = gridDim.x - 1 - blockIdx.x;  // heavy blocks first
    const int h = blockIdx.y;
    const int b = blockIdx.z;
    const int g = h >> 2;
    const int tid = threadIdx.x;
    const int wid = tid >> 5;
    const int lane = tid & 31;
    const int r = lane >> 2;
    const int tig = lane & 3;
    const int q0 = bq * 64;
    const int rq = wid * 16;
    const int ntile = bq + 1;

    const __half* qbase = Qh + (((size_t)b * NH + h) * SEQ + q0) * HDIM;
    const __half* kbase = Kh + ((size_t)b * NKV + g) * SEQ * HDIM;
    const __half* vbase = Vth + ((size_t)b * NKV + g) * HDIM * SEQ;

    // Prologue: Q + K/V tile 0
#pragma unroll
    for (int i = 0; i < 4; i++) {
        int cl = i * 128 + tid;
        int rr = cl >> 3, cc = cl & 7;
        int ph = rr * 64 + ((cc ^ (rr & 7)) << 3);
        CPASYNC16(&Qs[ph], qbase + rr * HDIM + cc * 8);
        CPASYNC16(&Ks[0][ph], kbase + rr * HDIM + cc * 8);
        CPASYNC16(&Vs[0][ph], vbase + (size_t)rr * SEQ + cc * 8);
    }
    asm volatile("cp.async.commit_group;");

    uint32_t qa[4][4];
    float m0 = -1e30f, m1 = -1e30f, l0 = 0.0f, l1 = 0.0f;
    float acc[8][4];
#pragma unroll
    for (int dt = 0; dt < 8; dt++)
#pragma unroll
        for (int i = 0; i < 4; i++) acc[dt][i] = 0.0f;

    for (int kt = 0; kt < ntile; kt++) {
        if (kt + 1 < ntile) {
            int nb = (kt + 1) & 1;
            const __half* kb = kbase + (size_t)(kt + 1) * 64 * HDIM;
            const __half* vb = vbase + (kt + 1) * 64;
#pragma unroll
            for (int i = 0; i < 4; i++) {
                int cl = i * 128 + tid;
                int rr = cl >> 3, cc = cl & 7;
                int ph = rr * 64 + ((cc ^ (rr & 7)) << 3);
                CPASYNC16(&Ks[nb][ph], kb + rr * HDIM + cc * 8);
                CPASYNC16(&Vs[nb][ph], vb + (size_t)rr * SEQ + cc * 8);
            }
        }
        asm volatile("cp.async.commit_group;");
        asm volatile("cp.async.wait_group 1;");
        __syncthreads();

        if (kt == 0) {  // Q smem ready (loaded with group 0)
#pragma unroll
            for (int kk = 0; kk < 4; kk++) {
                int c = kk * 16 + tig * 2;
                qa[kk][0] = *(const uint32_t*)&Qs[swi(rq + r, c)];
                qa[kk][1] = *(const uint32_t*)&Qs[swi(rq + r + 8, c)];
                qa[kk][2] = *(const uint32_t*)&Qs[swi(rq + r, c + 8)];
                qa[kk][3] = *(const uint32_t*)&Qs[swi(rq + r + 8, c + 8)];
            }
        }

        const __half* ks = Ks[kt & 1];
        const __half* vs = Vs[kt & 1];

        // S = Q K^T
        float s[8][4];
#pragma unroll
        for (int nt = 0; nt < 8; nt++) {
#pragma unroll
            for (int i = 0; i < 4; i++) s[nt][i] = 0.0f;
#pragma unroll
            for (int kk = 0; kk < 4; kk++) {
                uint32_t b0 = *(const uint32_t*)&ks[swi(nt * 8 + r, kk * 16 + tig * 2)];
                uint32_t b1 =
                    *(const uint32_t*)&ks[swi(nt * 8 + r, kk * 16 + 8 + tig * 2)];
                MMA16816(s[nt], qa[kk][0], qa[kk][1], qa[kk][2], qa[kk][3], b0, b1);
            }
        }

        // scale (+ causal mask on diagonal tile)
        if (kt == bq) {
            int row_lo = q0 + rq + r, row_hi = row_lo + 8;
#pragma unroll
            for (int nt = 0; nt < 8; nt++) {
                int col = kt * 64 + nt * 8 + tig * 2;
                s[nt][0] = (col > row_lo) ? -1e30f : s[nt][0] * SCL;
                s[nt][1] = (col + 1 > row_lo) ? -1e30f : s[nt][1] * SCL;
                s[nt][2] = (col > row_hi) ? -1e30f : s[nt][2] * SCL;
                s[nt][3] = (col + 1 > row_hi) ? -1e30f : s[nt][3] * SCL;
            }
        } else {
#pragma unroll
            for (int nt = 0; nt < 8; nt++)
#pragma unroll
                for (int i = 0; i < 4; i++) s[nt][i] *= SCL;
        }

        // online softmax (base-2)
        float mt0 = s[0][0], mt1 = s[0][2];
#pragma unroll
        for (int nt = 0; nt < 8; nt++) {
            mt0 = fmaxf(mt0, fmaxf(s[nt][0], s[nt][1]));
            mt1 = fmaxf(mt1, fmaxf(s[nt][2], s[nt][3]));
        }
        mt0 = fmaxf(mt0, __shfl_xor_sync(0xffffffffu, mt0, 1));
        mt0 = fmaxf(mt0, __shfl_xor_sync(0xffffffffu, mt0, 2));
        mt1 = fmaxf(mt1, __shfl_xor_sync(0xffffffffu, mt1, 1));
        mt1 = fmaxf(mt1, __shfl_xor_sync(0xffffffffu, mt1, 2));
        float mn0 = fmaxf(m0, mt0), mn1 = fmaxf(m1, mt1);
        float rs0 = fast_exp2(m0 - mn0), rs1 = fast_exp2(m1 - mn1);
        m0 = mn0;
        m1 = mn1;

        uint32_t ph[8][2];
        float sum0 = 0.0f, sum1 = 0.0f;
#pragma unroll
        for (int nt = 0; nt < 8; nt++) {
            float p0 = fast_exp2(s[nt][0] - mn0);
            float p1 = fast_exp2(s[nt][1] - mn0);
            float p2 = fast_exp2(s[nt][2] - mn1);
            float p3 = fast_exp2(s[nt][3] - mn1);
            sum0 += p0 + p1;
            sum1 += p2 + p3;
            __half2 h01 = __floats2half2_rn(p0, p1);
            __half2 h23 = __floats2half2_rn(p2, p3);
            ph[nt][0] = *(uint32_t*)&h01;
            ph[nt][1] = *(uint32_t*)&h23;
        }
        sum0 += __shfl_xor_sync(0xffffffffu, sum0, 1);
        sum0 += __shfl_xor_sync(0xffffffffu, sum0, 2);
        sum1 += __shfl_xor_sync(0xffffffffu, sum1, 1);
        sum1 += __shfl_xor_sync(0xffffffffu, sum1, 2);
        l0 = l0 * rs0 + sum0;
        l1 = l1 * rs1 + sum1;

#pragma unroll
        for (int dt = 0; dt < 8; dt++) {
            acc[dt][0] *= rs0;
            acc[dt][1] *= rs0;
            acc[dt][2] *= rs1;
            acc[dt][3] *= rs1;
        }

        // O += P @ V  (Vt stored [d][kv])
#pragma unroll
        for (int dt = 0; dt < 8; dt++) {
#pragma unroll
            for (int kk = 0; kk < 4; kk++) {
                uint32_t b0 = *(const uint32_t*)&vs[swi(dt * 8 + r, kk * 16 + tig * 2)];
                uint32_t b1 =
                    *(const uint32_t*)&vs[swi(dt * 8 + r, kk * 16 + 8 + tig * 2)];
                MMA16816(acc[dt], ph[2 * kk][0], ph[2 * kk][1], ph[2 * kk + 1][0],
                         ph[2 * kk + 1][1], b0, b1);
            }
        }
        __syncthreads();  // done with this buffer before it is refilled
    }

    // normalize + write fp16
    float inv0 = 1.0f / l0, inv1 = 1.0f / l1;
    __half* obase = Oh + ((size_t)b * SEQ + q0 + rq) * QDIM + h * HDIM;
#pragma unroll
    for (int dt = 0; dt < 8; dt++) {
        int col = dt * 8 + tig * 2;
        *(__half2*)(obase + (size_t)r * QDIM + col) =
            __floats2half2_rn(acc[dt][0] * inv0, acc[dt][1] * inv0);
        *(__half2*)(obase + (size_t)(r + 8) * QDIM + col) =
            __floats2half2_rn(acc[dt][2] * inv1, acc[dt][3] * inv1);
    }
}

// ---------------------------------------------------------------------------
// Launch
// ---------------------------------------------------------------------------
extern "C" void kernel_launch(void* const* d_in, const int* in_sizes, int n_in,
                              void* d_out, int out_size) {
    const float* x = (const float*)d_in[0];
    const float* wq = (const float*)d_in[1];
    const float* wk = (const float*)d_in[2];
    const float* wv = (const float*)d_in[3];
    const float* wo = (const float*)d_in[4];
    const float* fc = (const float*)d_in[5];
    const float* fs = (const float*)d_in[6];
    float* out = (float*)d_out;

    __half *xh, *attnh, *qh, *kh, *vth, *wqkvTh, *woTh;
    cudaGetSymbolAddress((void**)&xh, g_xh);
    cudaGetSymbolAddress((void**)&attnh, g_attnh);
    cudaGetSymbolAddress((void**)&qh, g_qh);
    cudaGetSymbolAddress((void**)&kh, g_kh);
    cudaGetSymbolAddress((void**)&vth, g_vth);
    cudaGetSymbolAddress((void**)&wqkvTh, g_wqkvTh);
    cudaGetSymbolAddress((void**)&woTh, g_woTh);

    // x -> fp16; weights -> concatenated [3072][2048] fp16 (wqT | wkT | wvT)
    {
        int n = TOKENS * DMODEL;
        f32_to_f16<<<(n / 4 + 255) / 256, 256>>>(x, xh, n);
    }
    transpose_f16<<<dim3(QDIM / 32, DMODEL / 32), dim3(32, 8)>>>(wq, wqkvTh, DMODEL,
                                                                 QDIM);
    transpose_f16<<<dim3(KVDIM / 32, DMODEL / 32), dim3(32, 8)>>>(
        wk, wqkvTh + (size_t)QDIM * DMODEL, DMODEL, KVDIM);
    transpose_f16<<<dim3(KVDIM / 32, DMODEL / 32), dim3(32, 8)>>>(
        wv, wqkvTh + (size_t)(QDIM + KVDIM) * DMODEL, DMODEL, KVDIM);
    transpose_f16<<<dim3(DMODEL / 32, QDIM / 32), dim3(32, 8)>>>(wo, woTh, QDIM,
                                                                 DMODEL);

    // Fused QKV projection: one GEMM, epilogue routes Q(RoPE)/K(RoPE)/V(transp)
    hgemm3<4><<<dim3(NQKV / 128, TOKENS / 128), 256>>>(
        xh, wqkvTh, qh, kh, vth, fc, fs, TOKENS, NQKV, DMODEL);

    // Flash attention (fp16 mma) -> attnh fp16
    flash_mma<<<dim3(SEQ / 64, NH, BSZ), 128>>>(qh, kh, vth, attnh);

    // Output projection -> fp32 out
    hgemm3<0><<<dim3(DMODEL / 128, TOKENS / 128), 256>>>(
        attnh, woTh, out, (__half*)0, (__half*)0, fc, fs, TOKENS, DMODEL, QDIM);
}

// round 12
// speedup vs baseline: 6.8758x; 1.0630x over previous
#include <cuda_runtime.h>
#include <cuda_fp16.h>
#include <cuda_bf16.h>
#include <math.h>
#include <stdint.h>

// Problem dims (fixed)
#define BSZ 2
#define SEQ 2048
#define DMODEL 2048
#define NH 32
#define NKV 8
#define HDIM 64
#define QDIM (NH * HDIM)    // 2048
#define KVDIM (NKV * HDIM)  // 512
#define TOKENS (BSZ * SEQ)  // 4096
#define NQKV (QDIM + 2 * KVDIM)  // 3072

// scale = 1/sqrt(64) * log2(e)
#define SCL 0.1803368801111204f

// Scratch (static device globals; allocation is forbidden)
__device__ __half g_xh[(size_t)TOKENS * DMODEL];
__device__ __half g_attnh[(size_t)TOKENS * QDIM];
__device__ __half g_qh[(size_t)TOKENS * QDIM];    // [B][NH][S][64]
__device__ __half g_kh[(size_t)TOKENS * KVDIM];   // [B][NKV][S][64]
__device__ __half g_vth[(size_t)TOKENS * KVDIM];  // [B][NKV][64][S]
__device__ __half g_wqkvTh[(size_t)NQKV * DMODEL];  // [3072][2048] = wqT|wkT|wvT
__device__ __half g_woTh[(size_t)DMODEL * QDIM];

#define MMA16816(d, a0, a1, a2, a3, b0, b1)                      \
    asm volatile(                                                \
        "mma.sync.aligned.m16n8k16.row.col.f32.f16.f16.f32 "     \
        "{%0,%1,%2,%3}, {%4,%5,%6,%7}, {%8,%9}, {%0,%1,%2,%3};"  \
        : "+f"((d)[0]), "+f"((d)[1]), "+f"((d)[2]), "+f"((d)[3]) \
        : "r"(a0), "r"(a1), "r"(a2), "r"(a3), "r"(b0), "r"(b1))

#define CPASYNC16(smem_half_ptr, gptr)                                   \
    asm volatile("cp.async.cg.shared.global [%0], [%1], 16;" ::"r"(      \
                     (uint32_t)__cvta_generic_to_shared(smem_half_ptr)), \
                 "l"(gptr))

// exp2 on FMA/ALU pipes (x <= 0 expected; clamped to >= -126)
__device__ __forceinline__ float fast_exp2(float x) {
    x = fmaxf(x, -126.0f);
    float z = x + 12582912.0f;  // 1.5 * 2^23
    int n = __float_as_int(z) << 23;
    float f = x - (z - 12582912.0f);  // f in [-0.5, 0.5]
    float y = 0.0013276471f;
    y = fmaf(y, f, 0.0096181993f);
    y = fmaf(y, f, 0.0555041086f);
    y = fmaf(y, f, 0.2402264923f);
    y = fmaf(y, f, 0.6931471825f);
    y = fmaf(y, f, 1.0f);
    return __int_as_float(__float_as_int(y) + n);
}

// swizzled index of half element (r, c) in a [64][64] tile
__device__ __forceinline__ int swi(int r, int c) {
    return r * 64 + ((((c >> 3) ^ (r & 7)) << 3) + (c & 7));
}

// ---------------------------------------------------------------------------
// hgemm4<MODE>: C = A[M,K] @ B[N,K]^T, fp16 in, fp32 accum.
// CTA 128x128, BK=32, 2-stage cp.async, 128 thr = 4 warps (2m x 2n),
// warp tile 64x64 (1.0 LDS per MMA), scalar LDS fragment loads, static smem.
// Epilogue:
//   MODE 0: fp32 C0[M,N]
//   MODE 4: fused QKV routing by column region:
//     col <  2048        : RoPE + fp16 head-major -> C0 (qh, NH heads)
//     2048 <= col < 2560 : RoPE + fp16 head-major -> C1 (kh, NKV heads)
//     col >= 2560        : fp16 transposed head-major -> C2 (vth, NKV heads)
// ---------------------------------------------------------------------------
template <int MODE>
__global__ __launch_bounds__(128) void hgemm4(const __half* __restrict__ A,
                                              const __half* __restrict__ B,
                                              void* __restrict__ C0,
                                              __half* __restrict__ C1,
                                              __half* __restrict__ C2,
                                              const float* __restrict__ fc,
                                              const float* __restrict__ fs, int M,
                                              int N, int K) {
    __shared__ __half As[2][128][32];
    __shared__ __half Bs[2][128][32];

    const int tid = threadIdx.x;
    const int wid = tid >> 5;
    const int lane = tid & 31;
    const int wm = wid & 1;   // 2 m-warps
    const int wn = wid >> 1;  // 2 n-warps
    const int r = lane >> 2;
    const int tig = lane & 3;
    const int bx = blockIdx.x;
    const int by = blockIdx.y;

    const __half* Ab = A + (size_t)by * 128 * K;
    const __half* Bb = B + (size_t)bx * 128 * K;

    float acc[4][8][4];
#pragma unroll
    for (int mt = 0; mt < 4; mt++)
#pragma unroll
        for (int nt = 0; nt < 8; nt++)
#pragma unroll
            for (int i = 0; i < 4; i++) acc[mt][nt][i] = 0.0f;

#define LOAD_TILE(buf, k0)                                                       \
    {                                                                            \
        for (int i = 0; i < 4; i++) {                                            \
            int cl = tid + i * 128;                                              \
            int row = cl >> 2;                                                   \
            int c = cl & 3;                                                      \
            int phys = (c ^ ((row >> 1) & 3)) * 8;                               \
            CPASYNC16(&As[buf][row][phys], Ab + (size_t)row * K + (k0) + c * 8); \
            CPASYNC16(&Bs[buf][row][phys], Bb + (size_t)row * K + (k0) + c * 8); \
        }                                                                        \
    }

    LOAD_TILE(0, 0);
    asm volatile("cp.async.commit_group;");

    const int nk = K >> 5;
    for (int kt = 0; kt < nk; kt++) {
        const int buf = kt & 1;
        if (kt + 1 < nk) LOAD_TILE(buf ^ 1, (kt + 1) * 32);
        asm volatile("cp.async.commit_group;");
        asm volatile("cp.async.wait_group 1;");
        __syncthreads();

#pragma unroll
        for (int ks = 0; ks < 2; ks++) {
            const int c0 = ks * 2, c1 = ks * 2 + 1;
            uint32_t a[4][4], b[8][2];
#pragma unroll
            for (int mt = 0; mt < 4; mt++) {
                int r0 = wm * 64 + mt * 16 + r;
                int r1 = r0 + 8;
                int s0 = (r0 >> 1) & 3, s1 = (r1 >> 1) & 3;
                a[mt][0] = *(const uint32_t*)&As[buf][r0][(c0 ^ s0) * 8 + tig * 2];
                a[mt][1] = *(const uint32_t*)&As[buf][r1][(c0 ^ s1) * 8 + tig * 2];
                a[mt][2] = *(const uint32_t*)&As[buf][r0][(c1 ^ s0) * 8 + tig * 2];
                a[mt][3] = *(const uint32_t*)&As[buf][r1][(c1 ^ s1) * 8 + tig * 2];
            }
#pragma unroll
            for (int nt = 0; nt < 8; nt++) {
                int n0 = wn * 64 + nt * 8 + r;
                int sn = (n0 >> 1) & 3;
                b[nt][0] = *(const uint32_t*)&Bs[buf][n0][(c0 ^ sn) * 8 + tig * 2];
                b[nt][1] = *(const uint32_t*)&Bs[buf][n0][(c1 ^ sn) * 8 + tig * 2];
            }
#pragma unroll
            for (int mt = 0; mt < 4; mt++)
#pragma unroll
                for (int nt = 0; nt < 8; nt++)
                    MMA16816(acc[mt][nt], a[mt][0], a[mt][1], a[mt][2], a[mt][3],
                             b[nt][0], b[nt][1]);
        }
        __syncthreads();
    }

    // Epilogue
#pragma unroll
    for (int mt = 0; mt < 4; mt++) {
        int row = by * 128 + wm * 64 + mt * 16 + r;  // rows row, row+8
#pragma unroll
        for (int nt = 0; nt < 8; nt++) {
            int col = bx * 128 + wn * 64 + nt * 8 + tig * 2;
            if (MODE == 0) {
                float* C = (float*)C0;
                *(float2*)&C[(size_t)row * N + col] =
                    make_float2(acc[mt][nt][0], acc[mt][nt][1]);
                *(float2*)&C[(size_t)(row + 8) * N + col] =
                    make_float2(acc[mt][nt][2], acc[mt][nt][3]);
            } else {  // MODE 4: fused QKV routing
                int b = row >> 11;
                int s = row & (SEQ - 1);
                if (col < QDIM + KVDIM) {
                    // Q or K: RoPE + head-major
                    __half* base;
                    int c2, nheads;
                    if (col < QDIM) {
                        base = (__half*)C0;
                        c2 = col;
                        nheads = NH;
                    } else {
                        base = C1;
                        c2 = col - QDIM;
                        nheads = NKV;
                    }
                    int h = c2 >> 6;
                    int d = c2 & 63;
                    int j = d >> 1;
                    __half* dst =
                        base + (((size_t)b * nheads + h) * SEQ + s) * HDIM + d;
                    float c0v = fc[s * 32 + j], s0v = fs[s * 32 + j];
                    float c1v = fc[(s + 8) * 32 + j], s1v = fs[(s + 8) * 32 + j];
                    *(__half2*)dst = __floats2half2_rn(
                        acc[mt][nt][0] * c0v - acc[mt][nt][1] * s0v,
                        acc[mt][nt][0] * s0v + acc[mt][nt][1] * c0v);
                    *(__half2*)(dst + 8 * HDIM) = __floats2half2_rn(
                        acc[mt][nt][2] * c1v - acc[mt][nt][3] * s1v,
                        acc[mt][nt][2] * s1v + acc[mt][nt][3] * c1v);
                } else {
                    // V: transposed head-major [b][g][d][S]
                    int c2 = col - QDIM - KVDIM;
                    int h = c2 >> 6;
                    int d = c2 & 63;
                    __half* dst = C2 + (((size_t)b * NKV + h) * HDIM + d) * SEQ + s;
                    dst[0] = __float2half_rn(acc[mt][nt][0]);
                    dst[SEQ] = __float2half_rn(acc[mt][nt][1]);
                    dst[8] = __float2half_rn(acc[mt][nt][2]);
                    dst[SEQ + 8] = __float2half_rn(acc[mt][nt][3]);
                }
            }
        }
    }
#undef LOAD_TILE
}

// ---------------------------------------------------------------------------
// fp32 -> fp16 elementwise convert (n divisible by 4)
// ---------------------------------------------------------------------------
__global__ void f32_to_f16(const float* __restrict__ in, __half* __restrict__ out,
                           int n) {
    int i = (blockIdx.x * blockDim.x + threadIdx.x) * 4;
    if (i >= n) return;
    float4 v = *(const float4*)(in + i);
    *(__half2*)(out + i) = __floats2half2_rn(v.x, v.y);
    *(__half2*)(out + i + 2) = __floats2half2_rn(v.z, v.w);
}

// ---------------------------------------------------------------------------
// Transpose + convert: out[C][R] (fp16) = in[R][C] (fp32)
// ---------------------------------------------------------------------------
__global__ void transpose_f16(const float* __restrict__ in, __half* __restrict__ out,
                              int R, int C) {
    __shared__ float t[32][33];
    int bx = blockIdx.x * 32, by = blockIdx.y * 32;
    int x = bx + threadIdx.x;
    for (int i = threadIdx.y; i < 32; i += 8)
        t[i][threadIdx.x] = in[(size_t)(by + i) * C + x];
    __syncthreads();
    int ox = by + threadIdx.x;
    for (int i = threadIdx.y; i < 32; i += 8)
        out[(size_t)(bx + i) * R + ox] = __float2half_rn(t[threadIdx.x][i]);
}

// ---------------------------------------------------------------------------
// Flash attention, fp16 mma.sync, causal, GQA (round-5/9/11 proven, verbatim).
// Block: 64 q-rows x 1 head; 128 threads (4 warps x m16).
// Qh [b][h][s][64], Kh [b][g][s][64], Vth [b][g][d][S]; out fp16 [tok][h*64+d].
// ---------------------------------------------------------------------------
__global__ __launch_bounds__(128) void flash_mma(const __half* __restrict__ Qh,
                                                 const __half* __restrict__ Kh,
                                                 const __half* __restrict__ Vth,
                                                 __half* __restrict__ Oh) {
    __shared__ __half Qs[64 * 64];
    __shared__ __half Ks[2][64 * 64];
    __shared__ __half Vs[2][64 * 64];

    const int bq = gridDim.x - 1 - blockIdx.x;  // heavy blocks first
    const int h = blockIdx.y;
    const int b = blockIdx.z;
    const int g = h >> 2;
    const int tid = threadIdx.x;
    const int wid = tid >> 5;
    const int lane = tid & 31;
    const int r = lane >> 2;
    const int tig = lane & 3;
    const int q0 = bq * 64;
    const int rq = wid * 16;
    const int ntile = bq + 1;

    const __half* qbase = Qh + (((size_t)b * NH + h) * SEQ + q0) * HDIM;
    const __half* kbase = Kh + ((size_t)b * NKV + g) * SEQ * HDIM;
    const __half* vbase = Vth + ((size_t)b * NKV + g) * HDIM * SEQ;

    // Prologue: Q + K/V tile 0
#pragma unroll
    for (int i = 0; i < 4; i++) {
        int cl = i * 128 + tid;
        int rr = cl >> 3, cc = cl & 7;
        int ph = rr * 64 + ((cc ^ (rr & 7)) << 3);
        CPASYNC16(&Qs[ph], qbase + rr * HDIM + cc * 8);
        CPASYNC16(&Ks[0][ph], kbase + rr * HDIM + cc * 8);
        CPASYNC16(&Vs[0][ph], vbase + (size_t)rr * SEQ + cc * 8);
    }
    asm volatile("cp.async.commit_group;");

    uint32_t qa[4][4];
    float m0 = -1e30f, m1 = -1e30f, l0 = 0.0f, l1 = 0.0f;
    float acc[8][4];
#pragma unroll
    for (int dt = 0; dt < 8; dt++)
#pragma unroll
        for (int i = 0; i < 4; i++) acc[dt][i] = 0.0f;

    for (int kt = 0; kt < ntile; kt++) {
        if (kt + 1 < ntile) {
            int nb = (kt + 1) & 1;
            const __half* kb = kbase + (size_t)(kt + 1) * 64 * HDIM;
            const __half* vb = vbase + (kt + 1) * 64;
#pragma unroll
            for (int i = 0; i < 4; i++) {
                int cl = i * 128 + tid;
                int rr = cl >> 3, cc = cl & 7;
                int ph = rr * 64 + ((cc ^ (rr & 7)) << 3);
                CPASYNC16(&Ks[nb][ph], kb + rr * HDIM + cc * 8);
                CPASYNC16(&Vs[nb][ph], vb + (size_t)rr * SEQ + cc * 8);
            }
        }
        asm volatile("cp.async.commit_group;");
        asm volatile("cp.async.wait_group 1;");
        __syncthreads();

        if (kt == 0) {  // Q smem ready (loaded with group 0)
#pragma unroll
            for (int kk = 0; kk < 4; kk++) {
                int c = kk * 16 + tig * 2;
                qa[kk][0] = *(const uint32_t*)&Qs[swi(rq + r, c)];
                qa[kk][1] = *(const uint32_t*)&Qs[swi(rq + r + 8, c)];
                qa[kk][2] = *(const uint32_t*)&Qs[swi(rq + r, c + 8)];
                qa[kk][3] = *(const uint32_t*)&Qs[swi(rq + r + 8, c + 8)];
            }
        }

        const __half* ks = Ks[kt & 1];
        const __half* vs = Vs[kt & 1];

        // S = Q K^T
        float s[8][4];
#pragma unroll
        for (int nt = 0; nt < 8; nt++) {
#pragma unroll
            for (int i = 0; i < 4; i++) s[nt][i] = 0.0f;
#pragma unroll
            for (int kk = 0; kk < 4; kk++) {
                uint32_t b0 = *(const uint32_t*)&ks[swi(nt * 8 + r, kk * 16 + tig * 2)];
                uint32_t b1 =
                    *(const uint32_t*)&ks[swi(nt * 8 + r, kk * 16 + 8 + tig * 2)];
                MMA16816(s[nt], qa[kk][0], qa[kk][1], qa[kk][2], qa[kk][3], b0, b1);
            }
        }

        // scale (+ causal mask on diagonal tile)
        if (kt == bq) {
            int row_lo = q0 + rq + r, row_hi = row_lo + 8;
#pragma unroll
            for (int nt = 0; nt < 8; nt++) {
                int col = kt * 64 + nt * 8 + tig * 2;
                s[nt][0] = (col > row_lo) ? -1e30f : s[nt][0] * SCL;
                s[nt][1] = (col + 1 > row_lo) ? -1e30f : s[nt][1] * SCL;
                s[nt][2] = (col > row_hi) ? -1e30f : s[nt][2] * SCL;
                s[nt][3] = (col + 1 > row_hi) ? -1e30f : s[nt][3] * SCL;
            }
        } else {
#pragma unroll
            for (int nt = 0; nt < 8; nt++)
#pragma unroll
                for (int i = 0; i < 4; i++) s[nt][i] *= SCL;
        }

        // online softmax (base-2)
        float mt0 = s[0][0], mt1 = s[0][2];
#pragma unroll
        for (int nt = 0; nt < 8; nt++) {
            mt0 = fmaxf(mt0, fmaxf(s[nt][0], s[nt][1]));
            mt1 = fmaxf(mt1, fmaxf(s[nt][2], s[nt][3]));
        }
        mt0 = fmaxf(mt0, __shfl_xor_sync(0xffffffffu, mt0, 1));
        mt0 = fmaxf(mt0, __shfl_xor_sync(0xffffffffu, mt0, 2));
        mt1 = fmaxf(mt1, __shfl_xor_sync(0xffffffffu, mt1, 1));
        mt1 = fmaxf(mt1, __shfl_xor_sync(0xffffffffu, mt1, 2));
        float mn0 = fmaxf(m0, mt0), mn1 = fmaxf(m1, mt1);
        float rs0 = fast_exp2(m0 - mn0), rs1 = fast_exp2(m1 - mn1);
        m0 = mn0;
        m1 = mn1;

        uint32_t ph[8][2];
        float sum0 = 0.0f, sum1 = 0.0f;
#pragma unroll
        for (int nt = 0; nt < 8; nt++) {
            float p0 = fast_exp2(s[nt][0] - mn0);
            float p1 = fast_exp2(s[nt][1] - mn0);
            float p2 = fast_exp2(s[nt][2] - mn1);
            float p3 = fast_exp2(s[nt][3] - mn1);
            sum0 += p0 + p1;
            sum1 += p2 + p3;
            __half2 h01 = __floats2half2_rn(p0, p1);
            __half2 h23 = __floats2half2_rn(p2, p3);
            ph[nt][0] = *(uint32_t*)&h01;
            ph[nt][1] = *(uint32_t*)&h23;
        }
        sum0 += __shfl_xor_sync(0xffffffffu, sum0, 1);
        sum0 += __shfl_xor_sync(0xffffffffu, sum0, 2);
        sum1 += __shfl_xor_sync(0xffffffffu, sum1, 1);
        sum1 += __shfl_xor_sync(0xffffffffu, sum1, 2);
        l0 = l0 * rs0 + sum0;
        l1 = l1 * rs1 + sum1;

#pragma unroll
        for (int dt = 0; dt < 8; dt++) {
            acc[dt][0] *= rs0;
            acc[dt][1] *= rs0;
            acc[dt][2] *= rs1;
            acc[dt][3] *= rs1;
        }

        // O += P @ V  (Vt stored [d][kv])
#pragma unroll
        for (int dt = 0; dt < 8; dt++) {
#pragma unroll
            for (int kk = 0; kk < 4; kk++) {
                uint32_t b0 = *(const uint32_t*)&vs[swi(dt * 8 + r, kk * 16 + tig * 2)];
                uint32_t b1 =
                    *(const uint32_t*)&vs[swi(dt * 8 + r, kk * 16 + 8 + tig * 2)];
                MMA16816(acc[dt], ph[2 * kk][0], ph[2 * kk][1], ph[2 * kk + 1][0],
                         ph[2 * kk + 1][1], b0, b1);
            }
        }
        __syncthreads();  // done with this buffer before it is refilled
    }

    // normalize + write fp16
    float inv0 = 1.0f / l0, inv1 = 1.0f / l1;
    __half* obase = Oh + ((size_t)b * SEQ + q0 + rq) * QDIM + h * HDIM;
#pragma unroll
    for (int dt = 0; dt < 8; dt++) {
        int col = dt * 8 + tig * 2;
        *(__half2*)(obase + (size_t)r * QDIM + col) =
            __floats2half2_rn(acc[dt][0] * inv0, acc[dt][1] * inv0);
        *(__half2*)(obase + (size_t)(r + 8) * QDIM + col) =
            __floats2half2_rn(acc[dt][2] * inv1, acc[dt][3] * inv1);
    }
}

// ---------------------------------------------------------------------------
// Launch
// ---------------------------------------------------------------------------
extern "C" void kernel_launch(void* const* d_in, const int* in_sizes, int n_in,
                              void* d_out, int out_size) {
    const float* x = (const float*)d_in[0];
    const float* wq = (const float*)d_in[1];
    const float* wk = (const float*)d_in[2];
    const float* wv = (const float*)d_in[3];
    const float* wo = (const float*)d_in[4];
    const float* fc = (const float*)d_in[5];
    const float* fs = (const float*)d_in[6];
    float* out = (float*)d_out;

    __half *xh, *attnh, *qh, *kh, *vth, *wqkvTh, *woTh;
    cudaGetSymbolAddress((void**)&xh, g_xh);
    cudaGetSymbolAddress((void**)&attnh, g_attnh);
    cudaGetSymbolAddress((void**)&qh, g_qh);
    cudaGetSymbolAddress((void**)&kh, g_kh);
    cudaGetSymbolAddress((void**)&vth, g_vth);
    cudaGetSymbolAddress((void**)&wqkvTh, g_wqkvTh);
    cudaGetSymbolAddress((void**)&woTh, g_woTh);

    // x -> fp16; weights -> concatenated [3072][2048] fp16 (wqT | wkT | wvT)
    {
        int n = TOKENS * DMODEL;
        f32_to_f16<<<(n / 4 + 255) / 256, 256>>>(x, xh, n);
    }
    transpose_f16<<<dim3(QDIM / 32, DMODEL / 32), dim3(32, 8)>>>(wq, wqkvTh, DMODEL,
                                                                 QDIM);
    transpose_f16<<<dim3(KVDIM / 32, DMODEL / 32), dim3(32, 8)>>>(
        wk, wqkvTh + (size_t)QDIM * DMODEL, DMODEL, KVDIM);
    transpose_f16<<<dim3(KVDIM / 32, DMODEL / 32), dim3(32, 8)>>>(
        wv, wqkvTh + (size_t)(QDIM + KVDIM) * DMODEL, DMODEL, KVDIM);
    transpose_f16<<<dim3(DMODEL / 32, QDIM / 32), dim3(32, 8)>>>(wo, woTh, QDIM,
                                                                 DMODEL);

    // Fused QKV projection: one GEMM, epilogue routes Q(RoPE)/K(RoPE)/V(transp)
    hgemm4<4><<<dim3(NQKV / 128, TOKENS / 128), 128>>>(
        xh, wqkvTh, qh, kh, vth, fc, fs, TOKENS, NQKV, DMODEL);

    // Flash attention (fp16 mma) -> attnh fp16
    flash_mma<<<dim3(SEQ / 64, NH, BSZ), 128>>>(qh, kh, vth, attnh);

    // Output projection -> fp32 out
    hgemm4<0><<<dim3(DMODEL / 128, TOKENS / 128), 128>>>(
        attnh, woTh, out, (__half*)0, (__half*)0, fc, fs, TOKENS, DMODEL, QDIM);
}